// round 7
// baseline (speedup 1.0000x reference)
#include <cuda_runtime.h>
#include <math.h>

// Problem constants
constexpr int Bn  = 2;
constexpr int Ln  = 2048;
constexpr int Dn  = 1024;
constexpr int Hn  = 16;
constexpr int DHn = 64;
constexpr int Mn  = Bn * Ln;   // 4096 rows

// Scratch (no cudaMalloc allowed) — 5 x 16MB
__device__ float g_h[(size_t)Mn * Dn];
__device__ float g_q[(size_t)Mn * Dn];
__device__ float g_k[(size_t)Mn * Dn];
__device__ float g_v[(size_t)Mn * Dn];
__device__ float g_o[(size_t)Mn * Dn];

// ---------------------------------------------------------------------------
// LayerNorm: one block per row, 256 threads, float4
// ---------------------------------------------------------------------------
__global__ __launch_bounds__(256) void ln_kernel(
    const float* __restrict__ x, const float* __restrict__ gamma,
    const float* __restrict__ beta, float* __restrict__ out)
{
    const int row = blockIdx.x;
    const int t   = threadIdx.x;
    const float4 xv = reinterpret_cast<const float4*>(x + (size_t)row * Dn)[t];
    float s  = xv.x + xv.y + xv.z + xv.w;
    float sq = xv.x * xv.x + xv.y * xv.y + xv.z * xv.z + xv.w * xv.w;
    #pragma unroll
    for (int off = 16; off; off >>= 1) {
        s  += __shfl_xor_sync(0xffffffffu, s,  off);
        sq += __shfl_xor_sync(0xffffffffu, sq, off);
    }
    __shared__ float sh[16];
    if ((t & 31) == 0) { sh[t >> 5] = s; sh[8 + (t >> 5)] = sq; }
    __syncthreads();
    float S = 0.f, SQ = 0.f;
    #pragma unroll
    for (int i = 0; i < 8; i++) { S += sh[i]; SQ += sh[8 + i]; }
    const float mu   = S * (1.0f / Dn);
    const float var  = SQ * (1.0f / Dn) - mu * mu;
    const float rstd = rsqrtf(var + 1e-5f);
    const float4 gv = reinterpret_cast<const float4*>(gamma)[t];
    const float4 bv = reinterpret_cast<const float4*>(beta)[t];
    float4 ov;
    ov.x = (xv.x - mu) * rstd * gv.x + bv.x;
    ov.y = (xv.y - mu) * rstd * gv.y + bv.y;
    ov.z = (xv.z - mu) * rstd * gv.z + bv.z;
    ov.w = (xv.w - mu) * rstd * gv.w + bv.w;
    reinterpret_cast<float4*>(out + (size_t)row * Dn)[t] = ov;
}

// ---------------------------------------------------------------------------
// SGEMM with bias: C[M,N] = A[M,K] @ B[K,N] + bias[N]
// BM=BN=128, BK=8, TM=TN=8, 256 threads.
// OUT_MODE 0: row-major [M,N].  OUT_MODE 1: head-split [B,H,L,DH].
// ---------------------------------------------------------------------------
template <int OUT_MODE>
__global__ __launch_bounds__(256) void sgemm_bias_kernel(
    const float* __restrict__ A, const float* __restrict__ B,
    const float* __restrict__ bias, float* __restrict__ C,
    int M, int N, int K)
{
    __shared__ float As[8][128];
    __shared__ float Bs[8][128];

    const int tid  = threadIdx.x;
    const int bm   = blockIdx.y * 128;
    const int bn   = blockIdx.x * 128;
    const int arow = tid >> 1;
    const int acol = (tid & 1) * 4;
    const int brow = tid >> 5;
    const int bcol = (tid & 31) * 4;
    const int ty   = tid >> 4;
    const int tx   = tid & 15;

    const float* Ap = A + (size_t)(bm + arow) * K + acol;
    const float* Bp = B + (size_t)brow * N + bn + bcol;

    float acc[8][8];
    #pragma unroll
    for (int i = 0; i < 8; i++)
        #pragma unroll
        for (int j = 0; j < 8; j++) acc[i][j] = 0.f;

    for (int k0 = 0; k0 < K; k0 += 8) {
        const float4 av = *reinterpret_cast<const float4*>(Ap + k0);
        As[acol + 0][arow] = av.x;
        As[acol + 1][arow] = av.y;
        As[acol + 2][arow] = av.z;
        As[acol + 3][arow] = av.w;
        *reinterpret_cast<float4*>(&Bs[brow][bcol]) =
            *reinterpret_cast<const float4*>(Bp + (size_t)k0 * N);
        __syncthreads();
        #pragma unroll
        for (int kk = 0; kk < 8; kk++) {
            float ra[8], rb[8];
            *reinterpret_cast<float4*>(&ra[0]) = *reinterpret_cast<float4*>(&As[kk][ty * 8]);
            *reinterpret_cast<float4*>(&ra[4]) = *reinterpret_cast<float4*>(&As[kk][ty * 8 + 4]);
            *reinterpret_cast<float4*>(&rb[0]) = *reinterpret_cast<float4*>(&Bs[kk][tx * 8]);
            *reinterpret_cast<float4*>(&rb[4]) = *reinterpret_cast<float4*>(&Bs[kk][tx * 8 + 4]);
            #pragma unroll
            for (int i = 0; i < 8; i++)
                #pragma unroll
                for (int j = 0; j < 8; j++)
                    acc[i][j] = fmaf(ra[i], rb[j], acc[i][j]);
        }
        __syncthreads();
    }

    #pragma unroll
    for (int i = 0; i < 8; i++) {
        const int m = bm + ty * 8 + i;
        #pragma unroll
        for (int j = 0; j < 8; j++) {
            const int n  = bn + tx * 8 + j;
            const float cv = acc[i][j] + bias[n];
            if (OUT_MODE == 0) {
                C[(size_t)m * N + n] = cv;
            } else {
                const int b_ = m >> 11;        // m / Ln
                const int l  = m & (Ln - 1);
                const int h  = n >> 6;         // n / DHn
                const int dh = n & 63;
                C[((((size_t)b_ * Hn + h) * Ln) + l) * DHn + dh] = cv;
            }
        }
    }
}

// ---------------------------------------------------------------------------
// Flash attention (causal), fp32. One block per (q-tile, head, batch).
// Br = Bc = 64, DH = 64. 256 threads = 16x16 grid of 4x4 register tiles.
// KsT stored d-major with XOR swizzle on float4 groups -> conflict-free reads.
// Output written directly in [B, L, D] layout for the final projection.
// ---------------------------------------------------------------------------
__global__ __launch_bounds__(256) void flash_kernel(
    const float* __restrict__ Q, const float* __restrict__ K,
    const float* __restrict__ V, float* __restrict__ O)
{
    extern __shared__ float smem[];
    float* Qs  = smem;          // [64][64]  row = query, col = d
    float* KsT = smem + 4096;   // [64][64]  row = d, col = key (swizzled)
    float* Vs  = smem + 8192;   // [64][64]  row = key, col = d
    float* Ps  = smem + 12288;  // [64][64]  row = query, col = key

    const int qt  = blockIdx.x;
    const int h   = blockIdx.y;
    const int b_  = blockIdx.z;
    const int tid = threadIdx.x;
    const int ty  = tid >> 4;
    const int tx  = tid & 15;

    const size_t base = ((size_t)b_ * Hn + h) * Ln * DHn;
    const float* Qb = Q + base;
    const float* Kb = K + base;
    const float* Vb = V + base;

    // Load Q tile (once)
    for (int e = tid; e < 1024; e += 256) {
        const int r  = e >> 4;
        const int c4 = (e & 15) << 2;
        *reinterpret_cast<float4*>(&Qs[r * 64 + c4]) =
            *reinterpret_cast<const float4*>(&Qb[(size_t)(qt * 64 + r) * DHn + c4]);
    }

    float m_[4], l_[4], o_[4][4];
    #pragma unroll
    for (int i = 0; i < 4; i++) {
        m_[i] = -1e30f;
        l_[i] = 0.f;
        #pragma unroll
        for (int j = 0; j < 4; j++) o_[i][j] = 0.f;
    }

    for (int kt = 0; kt <= qt; kt++) {
        __syncthreads();  // protect KsT/Vs/Ps from previous iteration readers
        // Load K tile (transposed + swizzled) and V tile
        for (int e = tid; e < 1024; e += 256) {
            const int r  = e >> 4;
            const int c4 = (e & 15) << 2;
            const float4 kv = *reinterpret_cast<const float4*>(
                &Kb[(size_t)(kt * 64 + r) * DHn + c4]);
            const int r4 = r >> 2, rr = r & 3;
            KsT[(c4 + 0) * 64 + (((r4 ^ (c4 + 0)) & 15) << 2) + rr] = kv.x;
            KsT[(c4 + 1) * 64 + (((r4 ^ (c4 + 1)) & 15) << 2) + rr] = kv.y;
            KsT[(c4 + 2) * 64 + (((r4 ^ (c4 + 2)) & 15) << 2) + rr] = kv.z;
            KsT[(c4 + 3) * 64 + (((r4 ^ (c4 + 3)) & 15) << 2) + rr] = kv.w;
            *reinterpret_cast<float4*>(&Vs[r * 64 + c4]) =
                *reinterpret_cast<const float4*>(&Vb[(size_t)(kt * 64 + r) * DHn + c4]);
        }
        __syncthreads();

        // S = Q K^T   (4x4 per thread)
        float s[4][4];
        #pragma unroll
        for (int i = 0; i < 4; i++)
            #pragma unroll
            for (int j = 0; j < 4; j++) s[i][j] = 0.f;

        #pragma unroll
        for (int d4 = 0; d4 < 16; d4++) {
            float qa[4][4];
            #pragma unroll
            for (int i = 0; i < 4; i++)
                *reinterpret_cast<float4*>(qa[i]) =
                    *reinterpret_cast<const float4*>(&Qs[(ty * 4 + i) * 64 + d4 * 4]);
            #pragma unroll
            for (int dd = 0; dd < 4; dd++) {
                const int d = d4 * 4 + dd;
                float ka[4];
                *reinterpret_cast<float4*>(ka) =
                    *reinterpret_cast<const float4*>(&KsT[d * 64 + ((tx ^ (d & 15)) << 2)]);
                #pragma unroll
                for (int i = 0; i < 4; i++)
                    #pragma unroll
                    for (int j = 0; j < 4; j++)
                        s[i][j] = fmaf(qa[i][dd], ka[j], s[i][j]);
            }
        }

        // scale + causal mask
        const float scale = 0.125f;  // 1/sqrt(64)
        if (kt == qt) {
            #pragma unroll
            for (int i = 0; i < 4; i++)
                #pragma unroll
                for (int j = 0; j < 4; j++) {
                    const int r = ty * 4 + i, c = tx * 4 + j;
                    s[i][j] = (c <= r) ? s[i][j] * scale : -1e30f;
                }
        } else {
            #pragma unroll
            for (int i = 0; i < 4; i++)
                #pragma unroll
                for (int j = 0; j < 4; j++) s[i][j] *= scale;
        }

        // Online softmax (row reductions across the 16 tx lanes of this half-warp)
        #pragma unroll
        for (int i = 0; i < 4; i++) {
            float mx = fmaxf(fmaxf(s[i][0], s[i][1]), fmaxf(s[i][2], s[i][3]));
            #pragma unroll
            for (int off = 8; off; off >>= 1)
                mx = fmaxf(mx, __shfl_xor_sync(0xffffffffu, mx, off));
            const float mnew  = fmaxf(m_[i], mx);
            const float alpha = __expf(m_[i] - mnew);
            float rs = 0.f;
            #pragma unroll
            for (int j = 0; j < 4; j++) {
                const float p = __expf(s[i][j] - mnew);
                s[i][j] = p;
                rs += p;
            }
            #pragma unroll
            for (int off = 8; off; off >>= 1)
                rs += __shfl_xor_sync(0xffffffffu, rs, off);
            l_[i] = l_[i] * alpha + rs;
            m_[i] = mnew;
            #pragma unroll
            for (int j = 0; j < 4; j++) o_[i][j] *= alpha;
        }

        // Store P
        #pragma unroll
        for (int i = 0; i < 4; i++)
            *reinterpret_cast<float4*>(&Ps[(ty * 4 + i) * 64 + tx * 4]) =
                make_float4(s[i][0], s[i][1], s[i][2], s[i][3]);
        __syncthreads();

        // O += P V
        #pragma unroll
        for (int j4 = 0; j4 < 16; j4++) {
            float pa[4][4];
            #pragma unroll
            for (int i = 0; i < 4; i++)
                *reinterpret_cast<float4*>(pa[i]) =
                    *reinterpret_cast<const float4*>(&Ps[(ty * 4 + i) * 64 + j4 * 4]);
            #pragma unroll
            for (int jj = 0; jj < 4; jj++) {
                float va[4];
                *reinterpret_cast<float4*>(va) =
                    *reinterpret_cast<const float4*>(&Vs[(j4 * 4 + jj) * 64 + tx * 4]);
                #pragma unroll
                for (int i = 0; i < 4; i++)
                    #pragma unroll
                    for (int j = 0; j < 4; j++)
                        o_[i][j] = fmaf(pa[i][jj], va[j], o_[i][j]);
            }
        }
    }

    // Epilogue: normalize and write in [B, L, D] layout
    #pragma unroll
    for (int i = 0; i < 4; i++) {
        const float inv = 1.0f / l_[i];
        const int q = qt * 64 + ty * 4 + i;
        const float4 ov = make_float4(o_[i][0] * inv, o_[i][1] * inv,
                                      o_[i][2] * inv, o_[i][3] * inv);
        *reinterpret_cast<float4*>(
            &O[((size_t)b_ * Ln + q) * Dn + h * DHn + tx * 4]) = ov;
    }
}

// ---------------------------------------------------------------------------
// kernel_launch
// ---------------------------------------------------------------------------
extern "C" void kernel_launch(void* const* d_in, const int* in_sizes, int n_in,
                              void* d_out, int out_size)
{
    const float* x    = (const float*)d_in[0];
    // d_in[1] = mask (causal, known statically) — ignored
    const float* ln_g = (const float*)d_in[2];
    const float* ln_b = (const float*)d_in[3];
    const float* Wq   = (const float*)d_in[4];
    const float* bq   = (const float*)d_in[5];
    const float* Wk   = (const float*)d_in[6];
    const float* bk   = (const float*)d_in[7];
    const float* Wv   = (const float*)d_in[8];
    const float* bv   = (const float*)d_in[9];
    const float* Wo   = (const float*)d_in[10];
    const float* bo   = (const float*)d_in[11];
    float* out = (float*)d_out;

    float *ph, *pq, *pk, *pv, *po;
    cudaGetSymbolAddress((void**)&ph, g_h);
    cudaGetSymbolAddress((void**)&pq, g_q);
    cudaGetSymbolAddress((void**)&pk, g_k);
    cudaGetSymbolAddress((void**)&pv, g_v);
    cudaGetSymbolAddress((void**)&po, g_o);

    // 1. LayerNorm
    ln_kernel<<<Mn, 256>>>(x, ln_g, ln_b, ph);

    // 2. QKV projections (write head-split [B,H,L,DH] layout)
    dim3 ggrid(Dn / 128, Mn / 128);
    sgemm_bias_kernel<1><<<ggrid, 256>>>(ph, Wq, bq, pq, Mn, Dn, Dn);
    sgemm_bias_kernel<1><<<ggrid, 256>>>(ph, Wk, bk, pk, Mn, Dn, Dn);
    sgemm_bias_kernel<1><<<ggrid, 256>>>(ph, Wv, bv, pv, Mn, Dn, Dn);

    // 3. Causal flash attention (writes [B,L,D] directly)
    cudaFuncSetAttribute(flash_kernel,
                         cudaFuncAttributeMaxDynamicSharedMemorySize, 65536);
    dim3 fgrid(Ln / 64, Hn, Bn);
    flash_kernel<<<fgrid, 256, 65536>>>(pq, pk, pv, po);

    // 4. Output projection
    sgemm_bias_kernel<0><<<ggrid, 256>>>(po, Wo, bo, out, Mn, Dn, Dn);
}

// round 8
// speedup vs baseline: 2.0461x; 2.0461x over previous
#include <cuda_runtime.h>
#include <math.h>
#include <stdint.h>

// Problem constants
constexpr int Bn  = 2;
constexpr int Ln  = 2048;
constexpr int Dn  = 1024;
constexpr int Hn  = 16;
constexpr int DHn = 64;
constexpr int Mn  = Bn * Ln;   // 4096 rows

// Scratch (no cudaMalloc allowed) — 5 x 16MB
__device__ float g_h[(size_t)Mn * Dn];
__device__ float g_q[(size_t)Mn * Dn];
__device__ float g_k[(size_t)Mn * Dn];
__device__ float g_v[(size_t)Mn * Dn];
__device__ float g_o[(size_t)Mn * Dn];

__device__ __forceinline__ uint32_t f2tf32(float f) {
    uint32_t u;
    asm("cvt.rna.tf32.f32 %0, %1;" : "=r"(u) : "f"(f));
    return u;
}

__device__ __forceinline__ void mma16n8k8(float* d, const uint32_t* a, const uint32_t* b) {
    asm volatile(
        "mma.sync.aligned.m16n8k8.row.col.f32.tf32.tf32.f32 "
        "{%0,%1,%2,%3}, {%4,%5,%6,%7}, {%8,%9}, {%0,%1,%2,%3};"
        : "+f"(d[0]), "+f"(d[1]), "+f"(d[2]), "+f"(d[3])
        : "r"(a[0]), "r"(a[1]), "r"(a[2]), "r"(a[3]), "r"(b[0]), "r"(b[1]));
}

// ---------------------------------------------------------------------------
// LayerNorm: one block per row, 256 threads, float4
// ---------------------------------------------------------------------------
__global__ __launch_bounds__(256) void ln_kernel(
    const float* __restrict__ x, const float* __restrict__ gamma,
    const float* __restrict__ beta, float* __restrict__ out)
{
    const int row = blockIdx.x;
    const int t   = threadIdx.x;
    const float4 xv = reinterpret_cast<const float4*>(x + (size_t)row * Dn)[t];
    float s  = xv.x + xv.y + xv.z + xv.w;
    float sq = xv.x * xv.x + xv.y * xv.y + xv.z * xv.z + xv.w * xv.w;
    #pragma unroll
    for (int off = 16; off; off >>= 1) {
        s  += __shfl_xor_sync(0xffffffffu, s,  off);
        sq += __shfl_xor_sync(0xffffffffu, sq, off);
    }
    __shared__ float sh[16];
    if ((t & 31) == 0) { sh[t >> 5] = s; sh[8 + (t >> 5)] = sq; }
    __syncthreads();
    float S = 0.f, SQ = 0.f;
    #pragma unroll
    for (int i = 0; i < 8; i++) { S += sh[i]; SQ += sh[8 + i]; }
    const float mu   = S * (1.0f / Dn);
    const float var  = SQ * (1.0f / Dn) - mu * mu;
    const float rstd = rsqrtf(var + 1e-5f);
    const float4 gv = reinterpret_cast<const float4*>(gamma)[t];
    const float4 bv = reinterpret_cast<const float4*>(beta)[t];
    float4 ov;
    ov.x = (xv.x - mu) * rstd * gv.x + bv.x;
    ov.y = (xv.y - mu) * rstd * gv.y + bv.y;
    ov.z = (xv.z - mu) * rstd * gv.z + bv.z;
    ov.w = (xv.w - mu) * rstd * gv.w + bv.w;
    reinterpret_cast<float4*>(out + (size_t)row * Dn)[t] = ov;
}

// ---------------------------------------------------------------------------
// TF32 tensor-core GEMM with bias: C[M,N] = A[M,K] @ B[K,N] + bias[N]
// M=4096, N=K=1024 (fixed). BM=BN=128, BK=32. 8 warps (2x4), each warp 64x32
// via m16n8k8 fragments (4 m-tiles x 4 n-tiles).
// OUT_MODE 0: row-major [M,N].  OUT_MODE 1: head-split [B,H,L,DH].
// ---------------------------------------------------------------------------
__device__ __forceinline__ size_t hs_addr(int m, int n) {
    // head-split address: [B, H, L, DH]
    const int b_ = m >> 11;          // m / Ln
    const int l  = m & (Ln - 1);
    const int h  = n >> 6;           // n / DHn
    const int dh = n & 63;
    return ((((size_t)b_ * Hn + h) * Ln) + l) * DHn + dh;
}

template <int OUT_MODE>
__global__ __launch_bounds__(256, 2) void tf32_gemm_kernel(
    const float* __restrict__ A, const float* __restrict__ B,
    const float* __restrict__ bias, float* __restrict__ C)
{
    // Padded strides chosen for conflict-free fragment LDS:
    // A stride 36: bank = (4g + t) -> all 32 distinct
    // B stride 136: bank = (8t + g) -> all 32 distinct
    __shared__ uint32_t As[128 * 36];
    __shared__ uint32_t Bs[32 * 136];

    const int tid  = threadIdx.x;
    const int bm   = blockIdx.y * 128;
    const int bn   = blockIdx.x * 128;
    const int wid  = tid >> 5;
    const int lane = tid & 31;
    const int wm   = (wid >> 2) * 64;   // 0 or 64
    const int wn   = (wid & 3) * 32;    // 0,32,64,96
    const int g    = lane >> 2;         // 0..7
    const int t4   = lane & 3;          // 0..3

    float acc[4][4][4];
    #pragma unroll
    for (int i = 0; i < 4; i++)
        #pragma unroll
        for (int j = 0; j < 4; j++)
            #pragma unroll
            for (int r = 0; r < 4; r++) acc[i][j][r] = 0.f;

    for (int k0 = 0; k0 < Dn; k0 += 32) {
        __syncthreads();
        // Fill A tile [128][32] and B tile [32][128], converting to tf32.
        #pragma unroll
        for (int i = 0; i < 4; i++) {
            const int e  = tid + i * 256;
            // A: r = e/8, c4 = (e%8)*4
            const int ar = e >> 3, ac4 = (e & 7) << 2;
            const float4 av = *reinterpret_cast<const float4*>(
                &A[(size_t)(bm + ar) * Dn + k0 + ac4]);
            uint4 au;
            au.x = f2tf32(av.x); au.y = f2tf32(av.y);
            au.z = f2tf32(av.z); au.w = f2tf32(av.w);
            *reinterpret_cast<uint4*>(&As[ar * 36 + ac4]) = au;
            // B: kb = e/32, n4 = (e%32)*4
            const int kb = e >> 5, n4 = (e & 31) << 2;
            const float4 bv = *reinterpret_cast<const float4*>(
                &B[(size_t)(k0 + kb) * Dn + bn + n4]);
            uint4 bu;
            bu.x = f2tf32(bv.x); bu.y = f2tf32(bv.y);
            bu.z = f2tf32(bv.z); bu.w = f2tf32(bv.w);
            *reinterpret_cast<uint4*>(&Bs[kb * 136 + n4]) = bu;
        }
        __syncthreads();

        #pragma unroll
        for (int ks = 0; ks < 4; ks++) {
            const int kk = ks * 8;
            uint32_t af[4][4];
            #pragma unroll
            for (int i = 0; i < 4; i++) {
                const int r = wm + i * 16 + g;
                af[i][0] = As[r * 36 + kk + t4];
                af[i][1] = As[(r + 8) * 36 + kk + t4];
                af[i][2] = As[r * 36 + kk + t4 + 4];
                af[i][3] = As[(r + 8) * 36 + kk + t4 + 4];
            }
            uint32_t bf[4][2];
            #pragma unroll
            for (int j = 0; j < 4; j++) {
                const int n = wn + j * 8 + g;
                bf[j][0] = Bs[(kk + t4) * 136 + n];
                bf[j][1] = Bs[(kk + t4 + 4) * 136 + n];
            }
            #pragma unroll
            for (int i = 0; i < 4; i++)
                #pragma unroll
                for (int j = 0; j < 4; j++)
                    mma16n8k8(acc[i][j], af[i], bf[j]);
        }
    }

    // Epilogue: bias + store. c0,c1 -> (row, col..col+1); c2,c3 -> (row+8, ..)
    #pragma unroll
    for (int i = 0; i < 4; i++) {
        #pragma unroll
        for (int j = 0; j < 4; j++) {
            const int m0 = bm + wm + i * 16 + g;
            const int n0 = bn + wn + j * 8 + t4 * 2;
            const float b0 = bias[n0], b1 = bias[n0 + 1];
            const float2 v0 = make_float2(acc[i][j][0] + b0, acc[i][j][1] + b1);
            const float2 v1 = make_float2(acc[i][j][2] + b0, acc[i][j][3] + b1);
            if (OUT_MODE == 0) {
                *reinterpret_cast<float2*>(&C[(size_t)m0 * Dn + n0])       = v0;
                *reinterpret_cast<float2*>(&C[(size_t)(m0 + 8) * Dn + n0]) = v1;
            } else {
                *reinterpret_cast<float2*>(&C[hs_addr(m0, n0)])     = v0;
                *reinterpret_cast<float2*>(&C[hs_addr(m0 + 8, n0)]) = v1;
            }
        }
    }
}

// ---------------------------------------------------------------------------
// Flash attention (causal), fp32. One block per (q-tile, head, batch).
// Br = Bc = 64, DH = 64. 256 threads = 16x16 grid of 4x4 register tiles.
// ---------------------------------------------------------------------------
__global__ __launch_bounds__(256) void flash_kernel(
    const float* __restrict__ Q, const float* __restrict__ K,
    const float* __restrict__ V, float* __restrict__ O)
{
    extern __shared__ float smem[];
    float* Qs  = smem;          // [64][64]  row = query, col = d
    float* KsT = smem + 4096;   // [64][64]  row = d, col = key (swizzled)
    float* Vs  = smem + 8192;   // [64][64]  row = key, col = d
    float* Ps  = smem + 12288;  // [64][64]  row = query, col = key

    const int qt  = blockIdx.x;
    const int h   = blockIdx.y;
    const int b_  = blockIdx.z;
    const int tid = threadIdx.x;
    const int ty  = tid >> 4;
    const int tx  = tid & 15;

    const size_t base = ((size_t)b_ * Hn + h) * Ln * DHn;
    const float* Qb = Q + base;
    const float* Kb = K + base;
    const float* Vb = V + base;

    for (int e = tid; e < 1024; e += 256) {
        const int r  = e >> 4;
        const int c4 = (e & 15) << 2;
        *reinterpret_cast<float4*>(&Qs[r * 64 + c4]) =
            *reinterpret_cast<const float4*>(&Qb[(size_t)(qt * 64 + r) * DHn + c4]);
    }

    float m_[4], l_[4], o_[4][4];
    #pragma unroll
    for (int i = 0; i < 4; i++) {
        m_[i] = -1e30f;
        l_[i] = 0.f;
        #pragma unroll
        for (int j = 0; j < 4; j++) o_[i][j] = 0.f;
    }

    for (int kt = 0; kt <= qt; kt++) {
        __syncthreads();
        for (int e = tid; e < 1024; e += 256) {
            const int r  = e >> 4;
            const int c4 = (e & 15) << 2;
            const float4 kv = *reinterpret_cast<const float4*>(
                &Kb[(size_t)(kt * 64 + r) * DHn + c4]);
            const int r4 = r >> 2, rr = r & 3;
            KsT[(c4 + 0) * 64 + (((r4 ^ (c4 + 0)) & 15) << 2) + rr] = kv.x;
            KsT[(c4 + 1) * 64 + (((r4 ^ (c4 + 1)) & 15) << 2) + rr] = kv.y;
            KsT[(c4 + 2) * 64 + (((r4 ^ (c4 + 2)) & 15) << 2) + rr] = kv.z;
            KsT[(c4 + 3) * 64 + (((r4 ^ (c4 + 3)) & 15) << 2) + rr] = kv.w;
            *reinterpret_cast<float4*>(&Vs[r * 64 + c4]) =
                *reinterpret_cast<const float4*>(&Vb[(size_t)(kt * 64 + r) * DHn + c4]);
        }
        __syncthreads();

        float s[4][4];
        #pragma unroll
        for (int i = 0; i < 4; i++)
            #pragma unroll
            for (int j = 0; j < 4; j++) s[i][j] = 0.f;

        #pragma unroll
        for (int d4 = 0; d4 < 16; d4++) {
            float qa[4][4];
            #pragma unroll
            for (int i = 0; i < 4; i++)
                *reinterpret_cast<float4*>(qa[i]) =
                    *reinterpret_cast<const float4*>(&Qs[(ty * 4 + i) * 64 + d4 * 4]);
            #pragma unroll
            for (int dd = 0; dd < 4; dd++) {
                const int d = d4 * 4 + dd;
                float ka[4];
                *reinterpret_cast<float4*>(ka) =
                    *reinterpret_cast<const float4*>(&KsT[d * 64 + ((tx ^ (d & 15)) << 2)]);
                #pragma unroll
                for (int i = 0; i < 4; i++)
                    #pragma unroll
                    for (int j = 0; j < 4; j++)
                        s[i][j] = fmaf(qa[i][dd], ka[j], s[i][j]);
            }
        }

        const float scale = 0.125f;  // 1/sqrt(64)
        if (kt == qt) {
            #pragma unroll
            for (int i = 0; i < 4; i++)
                #pragma unroll
                for (int j = 0; j < 4; j++) {
                    const int r = ty * 4 + i, c = tx * 4 + j;
                    s[i][j] = (c <= r) ? s[i][j] * scale : -1e30f;
                }
        } else {
            #pragma unroll
            for (int i = 0; i < 4; i++)
                #pragma unroll
                for (int j = 0; j < 4; j++) s[i][j] *= scale;
        }

        #pragma unroll
        for (int i = 0; i < 4; i++) {
            float mx = fmaxf(fmaxf(s[i][0], s[i][1]), fmaxf(s[i][2], s[i][3]));
            #pragma unroll
            for (int off = 8; off; off >>= 1)
                mx = fmaxf(mx, __shfl_xor_sync(0xffffffffu, mx, off));
            const float mnew  = fmaxf(m_[i], mx);
            const float alpha = __expf(m_[i] - mnew);
            float rs = 0.f;
            #pragma unroll
            for (int j = 0; j < 4; j++) {
                const float p = __expf(s[i][j] - mnew);
                s[i][j] = p;
                rs += p;
            }
            #pragma unroll
            for (int off = 8; off; off >>= 1)
                rs += __shfl_xor_sync(0xffffffffu, rs, off);
            l_[i] = l_[i] * alpha + rs;
            m_[i] = mnew;
            #pragma unroll
            for (int j = 0; j < 4; j++) o_[i][j] *= alpha;
        }

        #pragma unroll
        for (int i = 0; i < 4; i++)
            *reinterpret_cast<float4*>(&Ps[(ty * 4 + i) * 64 + tx * 4]) =
                make_float4(s[i][0], s[i][1], s[i][2], s[i][3]);
        __syncthreads();

        #pragma unroll
        for (int j4 = 0; j4 < 16; j4++) {
            float pa[4][4];
            #pragma unroll
            for (int i = 0; i < 4; i++)
                *reinterpret_cast<float4*>(pa[i]) =
                    *reinterpret_cast<const float4*>(&Ps[(ty * 4 + i) * 64 + j4 * 4]);
            #pragma unroll
            for (int jj = 0; jj < 4; jj++) {
                float va[4];
                *reinterpret_cast<float4*>(va) =
                    *reinterpret_cast<const float4*>(&Vs[(j4 * 4 + jj) * 64 + tx * 4]);
                #pragma unroll
                for (int i = 0; i < 4; i++)
                    #pragma unroll
                    for (int j = 0; j < 4; j++)
                        o_[i][j] = fmaf(pa[i][jj], va[j], o_[i][j]);
            }
        }
    }

    #pragma unroll
    for (int i = 0; i < 4; i++) {
        const float inv = 1.0f / l_[i];
        const int q = qt * 64 + ty * 4 + i;
        const float4 ov = make_float4(o_[i][0] * inv, o_[i][1] * inv,
                                      o_[i][2] * inv, o_[i][3] * inv);
        *reinterpret_cast<float4*>(
            &O[((size_t)b_ * Ln + q) * Dn + h * DHn + tx * 4]) = ov;
    }
}

// ---------------------------------------------------------------------------
// kernel_launch
// ---------------------------------------------------------------------------
extern "C" void kernel_launch(void* const* d_in, const int* in_sizes, int n_in,
                              void* d_out, int out_size)
{
    const float* x    = (const float*)d_in[0];
    // d_in[1] = mask (causal, known statically) — ignored
    const float* ln_g = (const float*)d_in[2];
    const float* ln_b = (const float*)d_in[3];
    const float* Wq   = (const float*)d_in[4];
    const float* bq   = (const float*)d_in[5];
    const float* Wk   = (const float*)d_in[6];
    const float* bk   = (const float*)d_in[7];
    const float* Wv   = (const float*)d_in[8];
    const float* bv   = (const float*)d_in[9];
    const float* Wo   = (const float*)d_in[10];
    const float* bo   = (const float*)d_in[11];
    float* out = (float*)d_out;

    float *ph, *pq, *pk, *pv, *po;
    cudaGetSymbolAddress((void**)&ph, g_h);
    cudaGetSymbolAddress((void**)&pq, g_q);
    cudaGetSymbolAddress((void**)&pk, g_k);
    cudaGetSymbolAddress((void**)&pv, g_v);
    cudaGetSymbolAddress((void**)&po, g_o);

    // 1. LayerNorm
    ln_kernel<<<Mn, 256>>>(x, ln_g, ln_b, ph);

    // 2. QKV projections (tensor cores, tf32; head-split [B,H,L,DH] output)
    dim3 ggrid(Dn / 128, Mn / 128);
    tf32_gemm_kernel<1><<<ggrid, 256>>>(ph, Wq, bq, pq);
    tf32_gemm_kernel<1><<<ggrid, 256>>>(ph, Wk, bk, pk);
    tf32_gemm_kernel<1><<<ggrid, 256>>>(ph, Wv, bv, pv);

    // 3. Causal flash attention (writes [B,L,D] directly)
    cudaFuncSetAttribute(flash_kernel,
                         cudaFuncAttributeMaxDynamicSharedMemorySize, 65536);
    dim3 fgrid(Ln / 64, Hn, Bn);
    flash_kernel<<<fgrid, 256, 65536>>>(pq, pk, pv, po);

    // 4. Output projection (row-major output)
    tf32_gemm_kernel<0><<<ggrid, 256>>>(po, Wo, bo, out);
}

// round 10
// speedup vs baseline: 3.6830x; 1.8000x over previous
#include <cuda_runtime.h>
#include <math.h>
#include <stdint.h>

// Problem constants
constexpr int Bn  = 2;
constexpr int Ln  = 2048;
constexpr int Dn  = 1024;
constexpr int Hn  = 16;
constexpr int DHn = 64;
constexpr int Mn  = Bn * Ln;   // 4096 rows

// Scratch (no cudaMalloc allowed) — 5 x 16MB
__device__ float g_h[(size_t)Mn * Dn];
__device__ float g_q[(size_t)Mn * Dn];
__device__ float g_k[(size_t)Mn * Dn];
__device__ float g_v[(size_t)Mn * Dn];
__device__ float g_o[(size_t)Mn * Dn];

__device__ __forceinline__ uint32_t f2tf32(float f) {
    uint32_t u;
    asm("cvt.rna.tf32.f32 %0, %1;" : "=r"(u) : "f"(f));
    return u;
}

__device__ __forceinline__ void mma16n8k8(float* d, const uint32_t* a, const uint32_t* b) {
    asm volatile(
        "mma.sync.aligned.m16n8k8.row.col.f32.tf32.tf32.f32 "
        "{%0,%1,%2,%3}, {%4,%5,%6,%7}, {%8,%9}, {%0,%1,%2,%3};"
        : "+f"(d[0]), "+f"(d[1]), "+f"(d[2]), "+f"(d[3])
        : "r"(a[0]), "r"(a[1]), "r"(a[2]), "r"(a[3]), "r"(b[0]), "r"(b[1]));
}

// ---------------------------------------------------------------------------
// LayerNorm: one block per row, 256 threads, float4
// ---------------------------------------------------------------------------
__global__ __launch_bounds__(256) void ln_kernel(
    const float* __restrict__ x, const float* __restrict__ gamma,
    const float* __restrict__ beta, float* __restrict__ out)
{
    const int row = blockIdx.x;
    const int t   = threadIdx.x;
    const float4 xv = reinterpret_cast<const float4*>(x + (size_t)row * Dn)[t];
    float s  = xv.x + xv.y + xv.z + xv.w;
    float sq = xv.x * xv.x + xv.y * xv.y + xv.z * xv.z + xv.w * xv.w;
    #pragma unroll
    for (int off = 16; off; off >>= 1) {
        s  += __shfl_xor_sync(0xffffffffu, s,  off);
        sq += __shfl_xor_sync(0xffffffffu, sq, off);
    }
    __shared__ float sh[16];
    if ((t & 31) == 0) { sh[t >> 5] = s; sh[8 + (t >> 5)] = sq; }
    __syncthreads();
    float S = 0.f, SQ = 0.f;
    #pragma unroll
    for (int i = 0; i < 8; i++) { S += sh[i]; SQ += sh[8 + i]; }
    const float mu   = S * (1.0f / Dn);
    const float var  = SQ * (1.0f / Dn) - mu * mu;
    const float rstd = rsqrtf(var + 1e-5f);
    const float4 gv = reinterpret_cast<const float4*>(gamma)[t];
    const float4 bv = reinterpret_cast<const float4*>(beta)[t];
    float4 ov;
    ov.x = (xv.x - mu) * rstd * gv.x + bv.x;
    ov.y = (xv.y - mu) * rstd * gv.y + bv.y;
    ov.z = (xv.z - mu) * rstd * gv.z + bv.z;
    ov.w = (xv.w - mu) * rstd * gv.w + bv.w;
    reinterpret_cast<float4*>(out + (size_t)row * Dn)[t] = ov;
}

// ---------------------------------------------------------------------------
// TF32 tensor-core GEMM with bias: C[M,N] = A[M,K] @ B[K,N] + bias[N]
// OUT_MODE 0: row-major [M,N] fp32.
// OUT_MODE 1: head-split [B,H,L,DH], values tf32-rounded (consumed by mma).
// ---------------------------------------------------------------------------
__device__ __forceinline__ size_t hs_addr(int m, int n) {
    const int b_ = m >> 11;
    const int l  = m & (Ln - 1);
    const int h  = n >> 6;
    const int dh = n & 63;
    return ((((size_t)b_ * Hn + h) * Ln) + l) * DHn + dh;
}

template <int OUT_MODE>
__global__ __launch_bounds__(256, 2) void tf32_gemm_kernel(
    const float* __restrict__ A, const float* __restrict__ B,
    const float* __restrict__ bias, float* __restrict__ C)
{
    __shared__ uint32_t As[128 * 36];
    __shared__ uint32_t Bs[32 * 136];

    const int tid  = threadIdx.x;
    const int bm   = blockIdx.y * 128;
    const int bn   = blockIdx.x * 128;
    const int wid  = tid >> 5;
    const int lane = tid & 31;
    const int wm   = (wid >> 2) * 64;
    const int wn   = (wid & 3) * 32;
    const int g    = lane >> 2;
    const int t4   = lane & 3;

    float acc[4][4][4];
    #pragma unroll
    for (int i = 0; i < 4; i++)
        #pragma unroll
        for (int j = 0; j < 4; j++)
            #pragma unroll
            for (int r = 0; r < 4; r++) acc[i][j][r] = 0.f;

    for (int k0 = 0; k0 < Dn; k0 += 32) {
        __syncthreads();
        #pragma unroll
        for (int i = 0; i < 4; i++) {
            const int e  = tid + i * 256;
            const int ar = e >> 3, ac4 = (e & 7) << 2;
            const float4 av = *reinterpret_cast<const float4*>(
                &A[(size_t)(bm + ar) * Dn + k0 + ac4]);
            uint4 au;
            au.x = f2tf32(av.x); au.y = f2tf32(av.y);
            au.z = f2tf32(av.z); au.w = f2tf32(av.w);
            *reinterpret_cast<uint4*>(&As[ar * 36 + ac4]) = au;
            const int kb = e >> 5, n4 = (e & 31) << 2;
            const float4 bv = *reinterpret_cast<const float4*>(
                &B[(size_t)(k0 + kb) * Dn + bn + n4]);
            uint4 bu;
            bu.x = f2tf32(bv.x); bu.y = f2tf32(bv.y);
            bu.z = f2tf32(bv.z); bu.w = f2tf32(bv.w);
            *reinterpret_cast<uint4*>(&Bs[kb * 136 + n4]) = bu;
        }
        __syncthreads();

        #pragma unroll
        for (int ks = 0; ks < 4; ks++) {
            const int kk = ks * 8;
            uint32_t af[4][4];
            #pragma unroll
            for (int i = 0; i < 4; i++) {
                const int r = wm + i * 16 + g;
                af[i][0] = As[r * 36 + kk + t4];
                af[i][1] = As[(r + 8) * 36 + kk + t4];
                af[i][2] = As[r * 36 + kk + t4 + 4];
                af[i][3] = As[(r + 8) * 36 + kk + t4 + 4];
            }
            uint32_t bf[4][2];
            #pragma unroll
            for (int j = 0; j < 4; j++) {
                const int n = wn + j * 8 + g;
                bf[j][0] = Bs[(kk + t4) * 136 + n];
                bf[j][1] = Bs[(kk + t4 + 4) * 136 + n];
            }
            #pragma unroll
            for (int i = 0; i < 4; i++)
                #pragma unroll
                for (int j = 0; j < 4; j++)
                    mma16n8k8(acc[i][j], af[i], bf[j]);
        }
    }

    #pragma unroll
    for (int i = 0; i < 4; i++) {
        #pragma unroll
        for (int j = 0; j < 4; j++) {
            const int m0 = bm + wm + i * 16 + g;
            const int n0 = bn + wn + j * 8 + t4 * 2;
            const float b0 = bias[n0], b1 = bias[n0 + 1];
            if (OUT_MODE == 0) {
                const float2 v0 = make_float2(acc[i][j][0] + b0, acc[i][j][1] + b1);
                const float2 v1 = make_float2(acc[i][j][2] + b0, acc[i][j][3] + b1);
                *reinterpret_cast<float2*>(&C[(size_t)m0 * Dn + n0])       = v0;
                *reinterpret_cast<float2*>(&C[(size_t)(m0 + 8) * Dn + n0]) = v1;
            } else {
                // tf32-rounded so the flash kernel can feed mma without cvt
                const float2 v0 = make_float2(
                    __uint_as_float(f2tf32(acc[i][j][0] + b0)),
                    __uint_as_float(f2tf32(acc[i][j][1] + b1)));
                const float2 v1 = make_float2(
                    __uint_as_float(f2tf32(acc[i][j][2] + b0)),
                    __uint_as_float(f2tf32(acc[i][j][3] + b1)));
                *reinterpret_cast<float2*>(&C[hs_addr(m0, n0)])     = v0;
                *reinterpret_cast<float2*>(&C[hs_addr(m0 + 8, n0)]) = v1;
            }
        }
    }
}

// ---------------------------------------------------------------------------
// Flash attention (causal) with tf32 tensor cores.
// Block = 128 threads = 4 warps; each warp owns 16 query rows.
// Tiles: Br=64, Bc=64, DH=64. S and PV both via mma.m16n8k8.
// P is staged through smem ALIASED onto the K buffer (K dead after S phase).
// Q/K/V in gmem are already tf32-rounded by the projection epilogue.
// ---------------------------------------------------------------------------
constexpr int QS_STR = 68;   // bank = 4g + t4  (conflict-free A/B frags)
constexpr int KS_STR = 68;
constexpr int VS_STR = 72;   // bank = 8t4 + g  (conflict-free V B-frags)

__global__ __launch_bounds__(128) void flash_tf32_kernel(
    const float* __restrict__ Q, const float* __restrict__ K,
    const float* __restrict__ V, float* __restrict__ O)
{
    extern __shared__ float smem[];
    float* Qs  = smem;                       // [64][68]
    float* KPs = smem + 64 * QS_STR;         // [64][68]  K tile, then P tile
    float* Vs  = KPs + 64 * KS_STR;          // [64][72]

    const int qt   = blockIdx.x;
    const int h    = blockIdx.y;
    const int b_   = blockIdx.z;
    const int tid  = threadIdx.x;
    const int wid  = tid >> 5;
    const int lane = tid & 31;
    const int g    = lane >> 2;     // 0..7
    const int t4   = lane & 3;      // 0..3
    const int m0   = wid * 16;      // warp's query-row base within tile

    const size_t base = ((size_t)b_ * Hn + h) * Ln * DHn;
    const float* Qb = Q + base;
    const float* Kb = K + base;
    const float* Vb = V + base;

    // Load Q tile once, pre-scaled by 1/sqrt(DH)=0.125 (exact power of two,
    // preserves tf32 rounding done by the GEMM epilogue).
    for (int e = tid; e < 1024; e += 128) {
        const int r  = e >> 4;
        const int c4 = (e & 15) << 2;
        float4 qv = *reinterpret_cast<const float4*>(
            &Qb[(size_t)(qt * 64 + r) * DHn + c4]);
        qv.x *= 0.125f; qv.y *= 0.125f; qv.z *= 0.125f; qv.w *= 0.125f;
        *reinterpret_cast<float4*>(&Qs[r * QS_STR + c4]) = qv;
    }

    float m1 = -1e30f, m2 = -1e30f, l1 = 0.f, l2 = 0.f;
    float o[8][4];
    #pragma unroll
    for (int nt = 0; nt < 8; nt++)
        #pragma unroll
        for (int r = 0; r < 4; r++) o[nt][r] = 0.f;

    for (int kt = 0; kt <= qt; kt++) {
        __syncthreads();   // previous iteration's Vs / P readers done
        for (int e = tid; e < 1024; e += 128) {
            const int r  = e >> 4;
            const int c4 = (e & 15) << 2;
            *reinterpret_cast<float4*>(&KPs[r * KS_STR + c4]) =
                *reinterpret_cast<const float4*>(
                    &Kb[(size_t)(kt * 64 + r) * DHn + c4]);
            *reinterpret_cast<float4*>(&Vs[r * VS_STR + c4]) =
                *reinterpret_cast<const float4*>(
                    &Vb[(size_t)(kt * 64 + r) * DHn + c4]);
        }
        __syncthreads();

        // ---- S = Q K^T (already scaled via Q) ----
        float s[8][4];
        #pragma unroll
        for (int nt = 0; nt < 8; nt++)
            #pragma unroll
            for (int r = 0; r < 4; r++) s[nt][r] = 0.f;

        #pragma unroll
        for (int ks = 0; ks < 8; ks++) {
            const int kk = ks * 8;
            uint32_t a[4];
            a[0] = __float_as_uint(Qs[(m0 + g)     * QS_STR + kk + t4]);
            a[1] = __float_as_uint(Qs[(m0 + g + 8) * QS_STR + kk + t4]);
            a[2] = __float_as_uint(Qs[(m0 + g)     * QS_STR + kk + t4 + 4]);
            a[3] = __float_as_uint(Qs[(m0 + g + 8) * QS_STR + kk + t4 + 4]);
            #pragma unroll
            for (int nt = 0; nt < 8; nt++) {
                uint32_t bfr[2];
                bfr[0] = __float_as_uint(KPs[(nt * 8 + g) * KS_STR + kk + t4]);
                bfr[1] = __float_as_uint(KPs[(nt * 8 + g) * KS_STR + kk + t4 + 4]);
                mma16n8k8(s[nt], a, bfr);
            }
        }

        // ---- causal mask on diagonal tile ----
        const int r1 = m0 + g, r2 = m0 + g + 8;
        if (kt == qt) {
            #pragma unroll
            for (int nt = 0; nt < 8; nt++) {
                const int c0 = nt * 8 + 2 * t4;
                if (c0     > r1) s[nt][0] = -1e30f;
                if (c0 + 1 > r1) s[nt][1] = -1e30f;
                if (c0     > r2) s[nt][2] = -1e30f;
                if (c0 + 1 > r2) s[nt][3] = -1e30f;
            }
        }

        // ---- online softmax (rows r1, r2; quad = 4 lanes sharing a row) ----
        float mx1 = -1e30f, mx2 = -1e30f;
        #pragma unroll
        for (int nt = 0; nt < 8; nt++) {
            mx1 = fmaxf(mx1, fmaxf(s[nt][0], s[nt][1]));
            mx2 = fmaxf(mx2, fmaxf(s[nt][2], s[nt][3]));
        }
        mx1 = fmaxf(mx1, __shfl_xor_sync(0xffffffffu, mx1, 1));
        mx1 = fmaxf(mx1, __shfl_xor_sync(0xffffffffu, mx1, 2));
        mx2 = fmaxf(mx2, __shfl_xor_sync(0xffffffffu, mx2, 1));
        mx2 = fmaxf(mx2, __shfl_xor_sync(0xffffffffu, mx2, 2));

        const float mn1 = fmaxf(m1, mx1);
        const float mn2 = fmaxf(m2, mx2);
        const float al1 = __expf(m1 - mn1);
        const float al2 = __expf(m2 - mn2);

        float rs1 = 0.f, rs2 = 0.f;
        #pragma unroll
        for (int nt = 0; nt < 8; nt++) {
            s[nt][0] = __expf(s[nt][0] - mn1); rs1 += s[nt][0];
            s[nt][1] = __expf(s[nt][1] - mn1); rs1 += s[nt][1];
            s[nt][2] = __expf(s[nt][2] - mn2); rs2 += s[nt][2];
            s[nt][3] = __expf(s[nt][3] - mn2); rs2 += s[nt][3];
        }
        rs1 += __shfl_xor_sync(0xffffffffu, rs1, 1);
        rs1 += __shfl_xor_sync(0xffffffffu, rs1, 2);
        rs2 += __shfl_xor_sync(0xffffffffu, rs2, 1);
        rs2 += __shfl_xor_sync(0xffffffffu, rs2, 2);

        l1 = l1 * al1 + rs1;  m1 = mn1;
        l2 = l2 * al2 + rs2;  m2 = mn2;

        #pragma unroll
        for (int nt = 0; nt < 8; nt++) {
            o[nt][0] *= al1; o[nt][1] *= al1;
            o[nt][2] *= al2; o[nt][3] *= al2;
        }

        // ---- stage P into KPs (K no longer needed) ----
        __syncthreads();   // all warps done reading K
        #pragma unroll
        for (int nt = 0; nt < 8; nt++) {
            float2 p01, p23;
            p01.x = __uint_as_float(f2tf32(s[nt][0]));
            p01.y = __uint_as_float(f2tf32(s[nt][1]));
            p23.x = __uint_as_float(f2tf32(s[nt][2]));
            p23.y = __uint_as_float(f2tf32(s[nt][3]));
            *reinterpret_cast<float2*>(&KPs[r1 * KS_STR + nt * 8 + 2 * t4]) = p01;
            *reinterpret_cast<float2*>(&KPs[r2 * KS_STR + nt * 8 + 2 * t4]) = p23;
        }
        __syncwarp();      // each warp reads only its own P rows

        // ---- O += P V ----
        #pragma unroll
        for (int ks = 0; ks < 8; ks++) {
            const int kk = ks * 8;
            uint32_t a[4];
            a[0] = __float_as_uint(KPs[(m0 + g)     * KS_STR + kk + t4]);
            a[1] = __float_as_uint(KPs[(m0 + g + 8) * KS_STR + kk + t4]);
            a[2] = __float_as_uint(KPs[(m0 + g)     * KS_STR + kk + t4 + 4]);
            a[3] = __float_as_uint(KPs[(m0 + g + 8) * KS_STR + kk + t4 + 4]);
            #pragma unroll
            for (int nt = 0; nt < 8; nt++) {
                uint32_t bfr[2];
                bfr[0] = __float_as_uint(Vs[(kk + t4)     * VS_STR + nt * 8 + g]);
                bfr[1] = __float_as_uint(Vs[(kk + t4 + 4) * VS_STR + nt * 8 + g]);
                mma16n8k8(o[nt], a, bfr);
            }
        }
    }

    // ---- epilogue: normalize, write [B, L, D] ----
    const float inv1 = 1.0f / l1;
    const float inv2 = 1.0f / l2;
    const int row1 = qt * 64 + m0 + g;
    const int row2 = row1 + 8;
    #pragma unroll
    for (int nt = 0; nt < 8; nt++) {
        const int col = h * DHn + nt * 8 + 2 * t4;
        *reinterpret_cast<float2*>(&O[((size_t)b_ * Ln + row1) * Dn + col]) =
            make_float2(o[nt][0] * inv1, o[nt][1] * inv1);
        *reinterpret_cast<float2*>(&O[((size_t)b_ * Ln + row2) * Dn + col]) =
            make_float2(o[nt][2] * inv2, o[nt][3] * inv2);
    }
}

// ---------------------------------------------------------------------------
// kernel_launch
// ---------------------------------------------------------------------------
extern "C" void kernel_launch(void* const* d_in, const int* in_sizes, int n_in,
                              void* d_out, int out_size)
{
    const float* x    = (const float*)d_in[0];
    // d_in[1] = mask (causal, known statically) — ignored
    const float* ln_g = (const float*)d_in[2];
    const float* ln_b = (const float*)d_in[3];
    const float* Wq   = (const float*)d_in[4];
    const float* bq   = (const float*)d_in[5];
    const float* Wk   = (const float*)d_in[6];
    const float* bk   = (const float*)d_in[7];
    const float* Wv   = (const float*)d_in[8];
    const float* bv   = (const float*)d_in[9];
    const float* Wo   = (const float*)d_in[10];
    const float* bo   = (const float*)d_in[11];
    float* out = (float*)d_out;

    float *ph, *pq, *pk, *pv, *po;
    cudaGetSymbolAddress((void**)&ph, g_h);
    cudaGetSymbolAddress((void**)&pq, g_q);
    cudaGetSymbolAddress((void**)&pk, g_k);
    cudaGetSymbolAddress((void**)&pv, g_v);
    cudaGetSymbolAddress((void**)&po, g_o);

    // 1. LayerNorm
    ln_kernel<<<Mn, 256>>>(x, ln_g, ln_b, ph);

    // 2. QKV projections (tf32 tensor cores; head-split tf32-rounded output)
    dim3 ggrid(Dn / 128, Mn / 128);
    tf32_gemm_kernel<1><<<ggrid, 256>>>(ph, Wq, bq, pq);
    tf32_gemm_kernel<1><<<ggrid, 256>>>(ph, Wk, bk, pk);
    tf32_gemm_kernel<1><<<ggrid, 256>>>(ph, Wv, bv, pv);

    // 3. Causal flash attention, tf32 tensor cores (writes [B,L,D])
    constexpr int FLASH_SMEM = (64 * QS_STR + 64 * KS_STR + 64 * VS_STR) * 4;
    cudaFuncSetAttribute(flash_tf32_kernel,
                         cudaFuncAttributeMaxDynamicSharedMemorySize, FLASH_SMEM);
    dim3 fgrid(Ln / 64, Hn, Bn);
    flash_tf32_kernel<<<fgrid, 128, FLASH_SMEM>>>(pq, pk, pv, po);

    // 4. Output projection (fp32 row-major output)
    tf32_gemm_kernel<0><<<ggrid, 256>>>(po, Wo, bo, out);
}

// round 11
// speedup vs baseline: 3.7836x; 1.0273x over previous
#include <cuda_runtime.h>
#include <math.h>
#include <stdint.h>

// Problem constants
constexpr int Bn  = 2;
constexpr int Ln  = 2048;
constexpr int Dn  = 1024;
constexpr int Hn  = 16;
constexpr int DHn = 64;
constexpr int Mn  = Bn * Ln;   // 4096 rows

// Scratch (no cudaMalloc allowed)
__device__ float g_h[(size_t)Mn * Dn];
__device__ float g_q[(size_t)Mn * Dn];
__device__ float g_k[(size_t)Mn * Dn];
__device__ float g_v[(size_t)Mn * Dn];
__device__ float g_o[(size_t)Mn * Dn];
__device__ float g_w[4 * (size_t)Dn * Dn];   // tf32-rounded Wq,Wk,Wv,Wo

__device__ __forceinline__ uint32_t f2tf32(float f) {
    uint32_t u;
    asm("cvt.rna.tf32.f32 %0, %1;" : "=r"(u) : "f"(f));
    return u;
}
__device__ __forceinline__ float rtf32(float f) {
    return __uint_as_float(f2tf32(f));
}

__device__ __forceinline__ void mma16n8k8(float* d, const uint32_t* a, const uint32_t* b) {
    asm volatile(
        "mma.sync.aligned.m16n8k8.row.col.f32.tf32.tf32.f32 "
        "{%0,%1,%2,%3}, {%4,%5,%6,%7}, {%8,%9}, {%0,%1,%2,%3};"
        : "+f"(d[0]), "+f"(d[1]), "+f"(d[2]), "+f"(d[3])
        : "r"(a[0]), "r"(a[1]), "r"(a[2]), "r"(a[3]), "r"(b[0]), "r"(b[1]));
}

__device__ __forceinline__ void cp_async16(uint32_t dst, const float* src) {
    asm volatile("cp.async.cg.shared.global [%0], [%1], 16;"
                 :: "r"(dst), "l"(src) : "memory");
}

// ---------------------------------------------------------------------------
// Weight pre-round: tf32(rna) all four projection matrices into g_w.
// ---------------------------------------------------------------------------
__global__ __launch_bounds__(256) void cvtw_kernel(
    const float* __restrict__ Wq, const float* __restrict__ Wk,
    const float* __restrict__ Wv, const float* __restrict__ Wo,
    float* __restrict__ dst)
{
    const float* srcs[4] = {Wq, Wk, Wv, Wo};
    const float* s = srcs[blockIdx.z];
    float* d = dst + (size_t)blockIdx.z * Dn * Dn;
    const int i = blockIdx.x * 256 + threadIdx.x;   // float4 index
    float4 v = reinterpret_cast<const float4*>(s)[i];
    v.x = rtf32(v.x); v.y = rtf32(v.y); v.z = rtf32(v.z); v.w = rtf32(v.w);
    reinterpret_cast<float4*>(d)[i] = v;
}

// ---------------------------------------------------------------------------
// LayerNorm: one block per row, 256 threads, float4. Output tf32-rounded.
// ---------------------------------------------------------------------------
__global__ __launch_bounds__(256) void ln_kernel(
    const float* __restrict__ x, const float* __restrict__ gamma,
    const float* __restrict__ beta, float* __restrict__ out)
{
    const int row = blockIdx.x;
    const int t   = threadIdx.x;
    const float4 xv = reinterpret_cast<const float4*>(x + (size_t)row * Dn)[t];
    float s  = xv.x + xv.y + xv.z + xv.w;
    float sq = xv.x * xv.x + xv.y * xv.y + xv.z * xv.z + xv.w * xv.w;
    #pragma unroll
    for (int off = 16; off; off >>= 1) {
        s  += __shfl_xor_sync(0xffffffffu, s,  off);
        sq += __shfl_xor_sync(0xffffffffu, sq, off);
    }
    __shared__ float sh[16];
    if ((t & 31) == 0) { sh[t >> 5] = s; sh[8 + (t >> 5)] = sq; }
    __syncthreads();
    float S = 0.f, SQ = 0.f;
    #pragma unroll
    for (int i = 0; i < 8; i++) { S += sh[i]; SQ += sh[8 + i]; }
    const float mu   = S * (1.0f / Dn);
    const float var  = SQ * (1.0f / Dn) - mu * mu;
    const float rstd = rsqrtf(var + 1e-5f);
    const float4 gv = reinterpret_cast<const float4*>(gamma)[t];
    const float4 bv = reinterpret_cast<const float4*>(beta)[t];
    float4 ov;
    ov.x = rtf32((xv.x - mu) * rstd * gv.x + bv.x);
    ov.y = rtf32((xv.y - mu) * rstd * gv.y + bv.y);
    ov.z = rtf32((xv.z - mu) * rstd * gv.z + bv.z);
    ov.w = rtf32((xv.w - mu) * rstd * gv.w + bv.w);
    reinterpret_cast<float4*>(out + (size_t)row * Dn)[t] = ov;
}

// ---------------------------------------------------------------------------
// TF32 GEMM core, 3-stage cp.async pipeline.
// C[M,N] = A @ B + bias. A,B already tf32-rounded in gmem.
// BM=BN=128, BK=32, 8 warps, warp tile 64x32 (m16n8k8).
// Stage layout in dynamic smem: [A 128x36 | B 32x136] = 8960 uints/stage.
// ---------------------------------------------------------------------------
constexpr int STG_U   = 8960;                 // uints per stage
constexpr int GEMM_SMEM = 3 * STG_U * 4;      // 107,520 B

__device__ __forceinline__ size_t hs_addr(int m, int n) {
    const int b_ = m >> 11;
    const int l  = m & (Ln - 1);
    const int h  = n >> 6;
    const int dh = n & 63;
    return ((((size_t)b_ * Hn + h) * Ln) + l) * DHn + dh;
}

template <int OUT_MODE>
__device__ __forceinline__ void gemm_core(
    const float* __restrict__ A, const float* __restrict__ B,
    const float* __restrict__ bias, float* __restrict__ C)
{
    extern __shared__ uint32_t gsm[];

    const int tid  = threadIdx.x;
    const int bm   = blockIdx.y * 128;
    const int bn   = blockIdx.x * 128;
    const int wid  = tid >> 5;
    const int lane = tid & 31;
    const int wm   = (wid >> 2) * 64;
    const int wn   = (wid & 3) * 32;
    const int g    = lane >> 2;
    const int t4   = lane & 3;

    const uint32_t smem_base = (uint32_t)__cvta_generic_to_shared(gsm);

    float acc[4][4][4];
    #pragma unroll
    for (int i = 0; i < 4; i++)
        #pragma unroll
        for (int j = 0; j < 4; j++)
            #pragma unroll
            for (int r = 0; r < 4; r++) acc[i][j][r] = 0.f;

    auto issue = [&](int t, int stage) {
        const uint32_t sb = smem_base + stage * (STG_U * 4);
        #pragma unroll
        for (int i = 0; i < 4; i++) {
            const int e  = tid + i * 256;
            const int ar = e >> 3, ac4 = (e & 7) << 2;
            cp_async16(sb + (ar * 36 + ac4) * 4,
                       A + (size_t)(bm + ar) * Dn + t * 32 + ac4);
            const int kb = e >> 5, n4 = (e & 31) << 2;
            cp_async16(sb + (4608 + kb * 136 + n4) * 4,
                       B + (size_t)(t * 32 + kb) * Dn + bn + n4);
        }
        asm volatile("cp.async.commit_group;" ::: "memory");
    };

    issue(0, 0);
    issue(1, 1);

    constexpr int NITER = Dn / 32;   // 32
    for (int t = 0; t < NITER; t++) {
        if (t < NITER - 1)
            asm volatile("cp.async.wait_group 1;" ::: "memory");
        else
            asm volatile("cp.async.wait_group 0;" ::: "memory");
        __syncthreads();
        if (t + 2 < NITER) issue(t + 2, (t + 2) % 3);

        const uint32_t* As = gsm + (t % 3) * STG_U;
        const uint32_t* Bs = As + 4608;

        #pragma unroll
        for (int ks = 0; ks < 4; ks++) {
            const int kk = ks * 8;
            uint32_t af[4][4];
            #pragma unroll
            for (int i = 0; i < 4; i++) {
                const int r = wm + i * 16 + g;
                af[i][0] = As[r * 36 + kk + t4];
                af[i][1] = As[(r + 8) * 36 + kk + t4];
                af[i][2] = As[r * 36 + kk + t4 + 4];
                af[i][3] = As[(r + 8) * 36 + kk + t4 + 4];
            }
            uint32_t bf[4][2];
            #pragma unroll
            for (int j = 0; j < 4; j++) {
                const int n = wn + j * 8 + g;
                bf[j][0] = Bs[(kk + t4) * 136 + n];
                bf[j][1] = Bs[(kk + t4 + 4) * 136 + n];
            }
            #pragma unroll
            for (int i = 0; i < 4; i++)
                #pragma unroll
                for (int j = 0; j < 4; j++)
                    mma16n8k8(acc[i][j], af[i], bf[j]);
        }
    }

    #pragma unroll
    for (int i = 0; i < 4; i++) {
        #pragma unroll
        for (int j = 0; j < 4; j++) {
            const int m0 = bm + wm + i * 16 + g;
            const int n0 = bn + wn + j * 8 + t4 * 2;
            const float b0 = bias[n0], b1 = bias[n0 + 1];
            if (OUT_MODE == 0) {
                const float2 v0 = make_float2(acc[i][j][0] + b0, acc[i][j][1] + b1);
                const float2 v1 = make_float2(acc[i][j][2] + b0, acc[i][j][3] + b1);
                *reinterpret_cast<float2*>(&C[(size_t)m0 * Dn + n0])       = v0;
                *reinterpret_cast<float2*>(&C[(size_t)(m0 + 8) * Dn + n0]) = v1;
            } else {
                const float2 v0 = make_float2(rtf32(acc[i][j][0] + b0),
                                              rtf32(acc[i][j][1] + b1));
                const float2 v1 = make_float2(rtf32(acc[i][j][2] + b0),
                                              rtf32(acc[i][j][3] + b1));
                *reinterpret_cast<float2*>(&C[hs_addr(m0, n0)])     = v0;
                *reinterpret_cast<float2*>(&C[hs_addr(m0 + 8, n0)]) = v1;
            }
        }
    }
}

struct QKVArgs {
    const float* W[3];
    const float* b[3];
    float*       out[3];
};

__global__ __launch_bounds__(256) void qkv_gemm_kernel(
    const float* __restrict__ A, QKVArgs args)
{
    const int z = blockIdx.z;
    gemm_core<1>(A, args.W[z], args.b[z], args.out[z]);
}

__global__ __launch_bounds__(256) void out_gemm_kernel(
    const float* __restrict__ A, const float* __restrict__ W,
    const float* __restrict__ bias, float* __restrict__ C)
{
    gemm_core<0>(A, W, bias, C);
}

// ---------------------------------------------------------------------------
// Flash attention (causal) with tf32 tensor cores.
// Block = 128 threads = 4 warps; each warp owns 16 query rows.
// qt order REVERSED so heavy (long) tiles launch first.
// ---------------------------------------------------------------------------
constexpr int QS_STR = 68;
constexpr int KS_STR = 68;
constexpr int VS_STR = 72;

__global__ __launch_bounds__(128) void flash_tf32_kernel(
    const float* __restrict__ Q, const float* __restrict__ K,
    const float* __restrict__ V, float* __restrict__ O)
{
    extern __shared__ float smem[];
    float* Qs  = smem;
    float* KPs = smem + 64 * QS_STR;
    float* Vs  = KPs + 64 * KS_STR;

    const int qt   = (Ln / 64 - 1) - blockIdx.x;   // heavy tiles first
    const int h    = blockIdx.y;
    const int b_   = blockIdx.z;
    const int tid  = threadIdx.x;
    const int wid  = tid >> 5;
    const int lane = tid & 31;
    const int g    = lane >> 2;
    const int t4   = lane & 3;
    const int m0   = wid * 16;

    const size_t base = ((size_t)b_ * Hn + h) * Ln * DHn;
    const float* Qb = Q + base;
    const float* Kb = K + base;
    const float* Vb = V + base;

    for (int e = tid; e < 1024; e += 128) {
        const int r  = e >> 4;
        const int c4 = (e & 15) << 2;
        float4 qv = *reinterpret_cast<const float4*>(
            &Qb[(size_t)(qt * 64 + r) * DHn + c4]);
        qv.x *= 0.125f; qv.y *= 0.125f; qv.z *= 0.125f; qv.w *= 0.125f;
        *reinterpret_cast<float4*>(&Qs[r * QS_STR + c4]) = qv;
    }

    float m1 = -1e30f, m2 = -1e30f, l1 = 0.f, l2 = 0.f;
    float o[8][4];
    #pragma unroll
    for (int nt = 0; nt < 8; nt++)
        #pragma unroll
        for (int r = 0; r < 4; r++) o[nt][r] = 0.f;

    for (int kt = 0; kt <= qt; kt++) {
        __syncthreads();
        for (int e = tid; e < 1024; e += 128) {
            const int r  = e >> 4;
            const int c4 = (e & 15) << 2;
            *reinterpret_cast<float4*>(&KPs[r * KS_STR + c4]) =
                *reinterpret_cast<const float4*>(
                    &Kb[(size_t)(kt * 64 + r) * DHn + c4]);
            *reinterpret_cast<float4*>(&Vs[r * VS_STR + c4]) =
                *reinterpret_cast<const float4*>(
                    &Vb[(size_t)(kt * 64 + r) * DHn + c4]);
        }
        __syncthreads();

        float s[8][4];
        #pragma unroll
        for (int nt = 0; nt < 8; nt++)
            #pragma unroll
            for (int r = 0; r < 4; r++) s[nt][r] = 0.f;

        #pragma unroll
        for (int ks = 0; ks < 8; ks++) {
            const int kk = ks * 8;
            uint32_t a[4];
            a[0] = __float_as_uint(Qs[(m0 + g)     * QS_STR + kk + t4]);
            a[1] = __float_as_uint(Qs[(m0 + g + 8) * QS_STR + kk + t4]);
            a[2] = __float_as_uint(Qs[(m0 + g)     * QS_STR + kk + t4 + 4]);
            a[3] = __float_as_uint(Qs[(m0 + g + 8) * QS_STR + kk + t4 + 4]);
            #pragma unroll
            for (int nt = 0; nt < 8; nt++) {
                uint32_t bfr[2];
                bfr[0] = __float_as_uint(KPs[(nt * 8 + g) * KS_STR + kk + t4]);
                bfr[1] = __float_as_uint(KPs[(nt * 8 + g) * KS_STR + kk + t4 + 4]);
                mma16n8k8(s[nt], a, bfr);
            }
        }

        const int r1 = m0 + g, r2 = m0 + g + 8;
        if (kt == qt) {
            #pragma unroll
            for (int nt = 0; nt < 8; nt++) {
                const int c0 = nt * 8 + 2 * t4;
                if (c0     > r1) s[nt][0] = -1e30f;
                if (c0 + 1 > r1) s[nt][1] = -1e30f;
                if (c0     > r2) s[nt][2] = -1e30f;
                if (c0 + 1 > r2) s[nt][3] = -1e30f;
            }
        }

        float mx1 = -1e30f, mx2 = -1e30f;
        #pragma unroll
        for (int nt = 0; nt < 8; nt++) {
            mx1 = fmaxf(mx1, fmaxf(s[nt][0], s[nt][1]));
            mx2 = fmaxf(mx2, fmaxf(s[nt][2], s[nt][3]));
        }
        mx1 = fmaxf(mx1, __shfl_xor_sync(0xffffffffu, mx1, 1));
        mx1 = fmaxf(mx1, __shfl_xor_sync(0xffffffffu, mx1, 2));
        mx2 = fmaxf(mx2, __shfl_xor_sync(0xffffffffu, mx2, 1));
        mx2 = fmaxf(mx2, __shfl_xor_sync(0xffffffffu, mx2, 2));

        const float mn1 = fmaxf(m1, mx1);
        const float mn2 = fmaxf(m2, mx2);
        const float al1 = __expf(m1 - mn1);
        const float al2 = __expf(m2 - mn2);

        float rs1 = 0.f, rs2 = 0.f;
        #pragma unroll
        for (int nt = 0; nt < 8; nt++) {
            s[nt][0] = __expf(s[nt][0] - mn1); rs1 += s[nt][0];
            s[nt][1] = __expf(s[nt][1] - mn1); rs1 += s[nt][1];
            s[nt][2] = __expf(s[nt][2] - mn2); rs2 += s[nt][2];
            s[nt][3] = __expf(s[nt][3] - mn2); rs2 += s[nt][3];
        }
        rs1 += __shfl_xor_sync(0xffffffffu, rs1, 1);
        rs1 += __shfl_xor_sync(0xffffffffu, rs1, 2);
        rs2 += __shfl_xor_sync(0xffffffffu, rs2, 1);
        rs2 += __shfl_xor_sync(0xffffffffu, rs2, 2);

        l1 = l1 * al1 + rs1;  m1 = mn1;
        l2 = l2 * al2 + rs2;  m2 = mn2;

        #pragma unroll
        for (int nt = 0; nt < 8; nt++) {
            o[nt][0] *= al1; o[nt][1] *= al1;
            o[nt][2] *= al2; o[nt][3] *= al2;
        }

        __syncthreads();   // all warps done reading K
        #pragma unroll
        for (int nt = 0; nt < 8; nt++) {
            float2 p01, p23;
            p01.x = rtf32(s[nt][0]);
            p01.y = rtf32(s[nt][1]);
            p23.x = rtf32(s[nt][2]);
            p23.y = rtf32(s[nt][3]);
            *reinterpret_cast<float2*>(&KPs[r1 * KS_STR + nt * 8 + 2 * t4]) = p01;
            *reinterpret_cast<float2*>(&KPs[r2 * KS_STR + nt * 8 + 2 * t4]) = p23;
        }
        __syncwarp();

        #pragma unroll
        for (int ks = 0; ks < 8; ks++) {
            const int kk = ks * 8;
            uint32_t a[4];
            a[0] = __float_as_uint(KPs[(m0 + g)     * KS_STR + kk + t4]);
            a[1] = __float_as_uint(KPs[(m0 + g + 8) * KS_STR + kk + t4]);
            a[2] = __float_as_uint(KPs[(m0 + g)     * KS_STR + kk + t4 + 4]);
            a[3] = __float_as_uint(KPs[(m0 + g + 8) * KS_STR + kk + t4 + 4]);
            #pragma unroll
            for (int nt = 0; nt < 8; nt++) {
                uint32_t bfr[2];
                bfr[0] = __float_as_uint(Vs[(kk + t4)     * VS_STR + nt * 8 + g]);
                bfr[1] = __float_as_uint(Vs[(kk + t4 + 4) * VS_STR + nt * 8 + g]);
                mma16n8k8(o[nt], a, bfr);
            }
        }
    }

    // Epilogue: normalize, tf32-round (feeds final GEMM via cp.async), write [B,L,D]
    const float inv1 = 1.0f / l1;
    const float inv2 = 1.0f / l2;
    const int row1 = qt * 64 + m0 + g;
    const int row2 = row1 + 8;
    #pragma unroll
    for (int nt = 0; nt < 8; nt++) {
        const int col = h * DHn + nt * 8 + 2 * t4;
        *reinterpret_cast<float2*>(&O[((size_t)b_ * Ln + row1) * Dn + col]) =
            make_float2(rtf32(o[nt][0] * inv1), rtf32(o[nt][1] * inv1));
        *reinterpret_cast<float2*>(&O[((size_t)b_ * Ln + row2) * Dn + col]) =
            make_float2(rtf32(o[nt][2] * inv2), rtf32(o[nt][3] * inv2));
    }
}

// ---------------------------------------------------------------------------
// kernel_launch
// ---------------------------------------------------------------------------
extern "C" void kernel_launch(void* const* d_in, const int* in_sizes, int n_in,
                              void* d_out, int out_size)
{
    const float* x    = (const float*)d_in[0];
    // d_in[1] = mask (causal, known statically) — ignored
    const float* ln_g = (const float*)d_in[2];
    const float* ln_b = (const float*)d_in[3];
    const float* Wq   = (const float*)d_in[4];
    const float* bq   = (const float*)d_in[5];
    const float* Wk   = (const float*)d_in[6];
    const float* bk   = (const float*)d_in[7];
    const float* Wv   = (const float*)d_in[8];
    const float* bv   = (const float*)d_in[9];
    const float* Wo   = (const float*)d_in[10];
    const float* bo   = (const float*)d_in[11];
    float* out = (float*)d_out;

    float *ph, *pq, *pk, *pv, *po, *pw;
    cudaGetSymbolAddress((void**)&ph, g_h);
    cudaGetSymbolAddress((void**)&pq, g_q);
    cudaGetSymbolAddress((void**)&pk, g_k);
    cudaGetSymbolAddress((void**)&pv, g_v);
    cudaGetSymbolAddress((void**)&po, g_o);
    cudaGetSymbolAddress((void**)&pw, g_w);

    cudaFuncSetAttribute(qkv_gemm_kernel,
                         cudaFuncAttributeMaxDynamicSharedMemorySize, GEMM_SMEM);
    cudaFuncSetAttribute(out_gemm_kernel,
                         cudaFuncAttributeMaxDynamicSharedMemorySize, GEMM_SMEM);
    constexpr int FLASH_SMEM = (64 * QS_STR + 64 * KS_STR + 64 * VS_STR) * 4;
    cudaFuncSetAttribute(flash_tf32_kernel,
                         cudaFuncAttributeMaxDynamicSharedMemorySize, FLASH_SMEM);

    // 0. Pre-round weights to tf32 (enables cvt-free cp.async GEMM mainloop)
    cvtw_kernel<<<dim3(Dn * Dn / 4 / 256, 1, 4), 256>>>(Wq, Wk, Wv, Wo, pw);

    // 1. LayerNorm (tf32-rounded output)
    ln_kernel<<<Mn, 256>>>(x, ln_g, ln_b, ph);

    // 2. QKV projections — single merged launch, grid.z selects matrix
    QKVArgs args;
    args.W[0] = pw;                 args.b[0] = bq;  args.out[0] = pq;
    args.W[1] = pw + (size_t)Dn*Dn; args.b[1] = bk;  args.out[1] = pk;
    args.W[2] = pw + 2*(size_t)Dn*Dn; args.b[2] = bv;  args.out[2] = pv;
    qkv_gemm_kernel<<<dim3(Dn / 128, Mn / 128, 3), 256, GEMM_SMEM>>>(ph, args);

    // 3. Causal flash attention, tf32 tensor cores (writes [B,L,D])
    dim3 fgrid(Ln / 64, Hn, Bn);
    flash_tf32_kernel<<<fgrid, 128, FLASH_SMEM>>>(pq, pk, pv, po);

    // 4. Output projection (fp32 row-major output)
    out_gemm_kernel<<<dim3(Dn / 128, Mn / 128), 256, GEMM_SMEM>>>(
        po, pw + 3*(size_t)Dn*Dn, bo, out);
}

// round 12
// speedup vs baseline: 4.0425x; 1.0684x over previous
#include <cuda_runtime.h>
#include <math.h>
#include <stdint.h>

// Problem constants
constexpr int Bn  = 2;
constexpr int Ln  = 2048;
constexpr int Dn  = 1024;
constexpr int Hn  = 16;
constexpr int DHn = 64;
constexpr int Mn  = Bn * Ln;   // 4096 rows

// Scratch (no cudaMalloc allowed)
__device__ float g_h[(size_t)Mn * Dn];
__device__ float g_q[(size_t)Mn * Dn];
__device__ float g_k[(size_t)Mn * Dn];
__device__ float g_v[(size_t)Mn * Dn];
__device__ float g_o[(size_t)Mn * Dn];
__device__ float g_w[4 * (size_t)Dn * Dn];   // tf32-rounded Wq,Wk,Wv,Wo

__device__ __forceinline__ uint32_t f2tf32(float f) {
    uint32_t u;
    asm("cvt.rna.tf32.f32 %0, %1;" : "=r"(u) : "f"(f));
    return u;
}
__device__ __forceinline__ float rtf32(float f) {
    return __uint_as_float(f2tf32(f));
}

__device__ __forceinline__ void mma16n8k8(float* d, const uint32_t* a, const uint32_t* b) {
    asm volatile(
        "mma.sync.aligned.m16n8k8.row.col.f32.tf32.tf32.f32 "
        "{%0,%1,%2,%3}, {%4,%5,%6,%7}, {%8,%9}, {%0,%1,%2,%3};"
        : "+f"(d[0]), "+f"(d[1]), "+f"(d[2]), "+f"(d[3])
        : "r"(a[0]), "r"(a[1]), "r"(a[2]), "r"(a[3]), "r"(b[0]), "r"(b[1]));
}

__device__ __forceinline__ void cp_async16(uint32_t dst, const float* src) {
    asm volatile("cp.async.cg.shared.global [%0], [%1], 16;"
                 :: "r"(dst), "l"(src) : "memory");
}

// ---------------------------------------------------------------------------
// Weight pre-round: tf32(rna) all four projection matrices into g_w.
// ---------------------------------------------------------------------------
__global__ __launch_bounds__(256) void cvtw_kernel(
    const float* __restrict__ Wq, const float* __restrict__ Wk,
    const float* __restrict__ Wv, const float* __restrict__ Wo,
    float* __restrict__ dst)
{
    const float* srcs[4] = {Wq, Wk, Wv, Wo};
    const float* s = srcs[blockIdx.z];
    float* d = dst + (size_t)blockIdx.z * Dn * Dn;
    const int i = blockIdx.x * 256 + threadIdx.x;   // float4 index
    float4 v = reinterpret_cast<const float4*>(s)[i];
    v.x = rtf32(v.x); v.y = rtf32(v.y); v.z = rtf32(v.z); v.w = rtf32(v.w);
    reinterpret_cast<float4*>(d)[i] = v;
}

// ---------------------------------------------------------------------------
// LayerNorm: one block per row, 256 threads, float4. Output tf32-rounded.
// ---------------------------------------------------------------------------
__global__ __launch_bounds__(256) void ln_kernel(
    const float* __restrict__ x, const float* __restrict__ gamma,
    const float* __restrict__ beta, float* __restrict__ out)
{
    const int row = blockIdx.x;
    const int t   = threadIdx.x;
    const float4 xv = reinterpret_cast<const float4*>(x + (size_t)row * Dn)[t];
    float s  = xv.x + xv.y + xv.z + xv.w;
    float sq = xv.x * xv.x + xv.y * xv.y + xv.z * xv.z + xv.w * xv.w;
    #pragma unroll
    for (int off = 16; off; off >>= 1) {
        s  += __shfl_xor_sync(0xffffffffu, s,  off);
        sq += __shfl_xor_sync(0xffffffffu, sq, off);
    }
    __shared__ float sh[16];
    if ((t & 31) == 0) { sh[t >> 5] = s; sh[8 + (t >> 5)] = sq; }
    __syncthreads();
    float S = 0.f, SQ = 0.f;
    #pragma unroll
    for (int i = 0; i < 8; i++) { S += sh[i]; SQ += sh[8 + i]; }
    const float mu   = S * (1.0f / Dn);
    const float var  = SQ * (1.0f / Dn) - mu * mu;
    const float rstd = rsqrtf(var + 1e-5f);
    const float4 gv = reinterpret_cast<const float4*>(gamma)[t];
    const float4 bv = reinterpret_cast<const float4*>(beta)[t];
    float4 ov;
    ov.x = rtf32((xv.x - mu) * rstd * gv.x + bv.x);
    ov.y = rtf32((xv.y - mu) * rstd * gv.y + bv.y);
    ov.z = rtf32((xv.z - mu) * rstd * gv.z + bv.z);
    ov.w = rtf32((xv.w - mu) * rstd * gv.w + bv.w);
    reinterpret_cast<float4*>(out + (size_t)row * Dn)[t] = ov;
}

// ---------------------------------------------------------------------------
// TF32 GEMM v3: BM=BN=128, BK=32, 128 threads = 4 warps (2x2),
// warp tile 64x64 (4 m-tiles x 8 n-tiles of m16n8k8). 3-stage cp.async.
// A,B already tf32-rounded in gmem.
// ---------------------------------------------------------------------------
constexpr int STG_U   = 8960;                 // uints per stage (A 128x36 | B 32x136)
constexpr int GEMM_SMEM = 3 * STG_U * 4;      // 107,520 B

__device__ __forceinline__ size_t hs_addr(int m, int n) {
    const int b_ = m >> 11;
    const int l  = m & (Ln - 1);
    const int h  = n >> 6;
    const int dh = n & 63;
    return ((((size_t)b_ * Hn + h) * Ln) + l) * DHn + dh;
}

template <int OUT_MODE>
__device__ __forceinline__ void gemm_core(
    const float* __restrict__ A, const float* __restrict__ B,
    const float* __restrict__ bias, float* __restrict__ C)
{
    extern __shared__ uint32_t gsm[];

    const int tid  = threadIdx.x;
    const int bm   = blockIdx.y * 128;
    const int bn   = blockIdx.x * 128;
    const int wid  = tid >> 5;
    const int lane = tid & 31;
    const int wm   = (wid >> 1) * 64;   // 0 or 64
    const int wn   = (wid & 1) * 64;    // 0 or 64
    const int g    = lane >> 2;
    const int t4   = lane & 3;

    const uint32_t smem_base = (uint32_t)__cvta_generic_to_shared(gsm);

    float acc[4][8][4];
    #pragma unroll
    for (int i = 0; i < 4; i++)
        #pragma unroll
        for (int j = 0; j < 8; j++)
            #pragma unroll
            for (int r = 0; r < 4; r++) acc[i][j][r] = 0.f;

    auto issue = [&](int t, int stage) {
        const uint32_t sb = smem_base + stage * (STG_U * 4);
        #pragma unroll
        for (int i = 0; i < 8; i++) {
            const int e  = tid + i * 128;
            const int ar = e >> 3, ac4 = (e & 7) << 2;
            cp_async16(sb + (ar * 36 + ac4) * 4,
                       A + (size_t)(bm + ar) * Dn + t * 32 + ac4);
            const int kb = e >> 5, n4 = (e & 31) << 2;
            cp_async16(sb + (4608 + kb * 136 + n4) * 4,
                       B + (size_t)(t * 32 + kb) * Dn + bn + n4);
        }
        asm volatile("cp.async.commit_group;" ::: "memory");
    };

    issue(0, 0);
    issue(1, 1);

    constexpr int NITER = Dn / 32;   // 32
    for (int t = 0; t < NITER; t++) {
        if (t < NITER - 1)
            asm volatile("cp.async.wait_group 1;" ::: "memory");
        else
            asm volatile("cp.async.wait_group 0;" ::: "memory");
        __syncthreads();
        if (t + 2 < NITER) issue(t + 2, (t + 2) % 3);

        const uint32_t* As = gsm + (t % 3) * STG_U;
        const uint32_t* Bs = As + 4608;

        #pragma unroll
        for (int ks = 0; ks < 4; ks++) {
            const int kk = ks * 8;
            uint32_t af[4][4];
            #pragma unroll
            for (int i = 0; i < 4; i++) {
                const int r = wm + i * 16 + g;
                af[i][0] = As[r * 36 + kk + t4];
                af[i][1] = As[(r + 8) * 36 + kk + t4];
                af[i][2] = As[r * 36 + kk + t4 + 4];
                af[i][3] = As[(r + 8) * 36 + kk + t4 + 4];
            }
            uint32_t bf[8][2];
            #pragma unroll
            for (int j = 0; j < 8; j++) {
                const int n = wn + j * 8 + g;
                bf[j][0] = Bs[(kk + t4) * 136 + n];
                bf[j][1] = Bs[(kk + t4 + 4) * 136 + n];
            }
            #pragma unroll
            for (int i = 0; i < 4; i++)
                #pragma unroll
                for (int j = 0; j < 8; j++)
                    mma16n8k8(acc[i][j], af[i], bf[j]);
        }
    }

    #pragma unroll
    for (int i = 0; i < 4; i++) {
        #pragma unroll
        for (int j = 0; j < 8; j++) {
            const int m0 = bm + wm + i * 16 + g;
            const int n0 = bn + wn + j * 8 + t4 * 2;
            const float b0 = bias[n0], b1 = bias[n0 + 1];
            if (OUT_MODE == 0) {
                const float2 v0 = make_float2(acc[i][j][0] + b0, acc[i][j][1] + b1);
                const float2 v1 = make_float2(acc[i][j][2] + b0, acc[i][j][3] + b1);
                *reinterpret_cast<float2*>(&C[(size_t)m0 * Dn + n0])       = v0;
                *reinterpret_cast<float2*>(&C[(size_t)(m0 + 8) * Dn + n0]) = v1;
            } else {
                const float2 v0 = make_float2(rtf32(acc[i][j][0] + b0),
                                              rtf32(acc[i][j][1] + b1));
                const float2 v1 = make_float2(rtf32(acc[i][j][2] + b0),
                                              rtf32(acc[i][j][3] + b1));
                *reinterpret_cast<float2*>(&C[hs_addr(m0, n0)])     = v0;
                *reinterpret_cast<float2*>(&C[hs_addr(m0 + 8, n0)]) = v1;
            }
        }
    }
}

struct QKVArgs {
    const float* W[3];
    const float* b[3];
    float*       out[3];
};

__global__ __launch_bounds__(128, 2) void qkv_gemm_kernel(
    const float* __restrict__ A, QKVArgs args)
{
    const int z = blockIdx.z;
    gemm_core<1>(A, args.W[z], args.b[z], args.out[z]);
}

__global__ __launch_bounds__(128, 2) void out_gemm_kernel(
    const float* __restrict__ A, const float* __restrict__ W,
    const float* __restrict__ bias, float* __restrict__ C)
{
    gemm_core<0>(A, W, bias, C);
}

// ---------------------------------------------------------------------------
// Flash attention v2 (causal), tf32 tensor cores.
// Br=128, Bc=64. 128 threads = 4 warps, each warp owns 32 query rows
// (warp-M=32 halves K/V fragment bytes per flop vs warp-M=16).
// smem: Q[128][68] + K[64][68] + V[64][72] + P[128][68] = 105,472 B -> 2 CTA/SM
// ---------------------------------------------------------------------------
constexpr int FQ_STR = 68;
constexpr int FK_STR = 68;
constexpr int FV_STR = 72;
constexpr int FP_STR = 68;
constexpr int FLASH_SMEM =
    (128 * FQ_STR + 64 * FK_STR + 64 * FV_STR + 128 * FP_STR) * 4;

__global__ __launch_bounds__(128, 2) void flash_tf32_kernel(
    const float* __restrict__ Q, const float* __restrict__ K,
    const float* __restrict__ V, float* __restrict__ O)
{
    extern __shared__ float smem[];
    float* Qs = smem;                         // [128][68]
    float* Ks = smem + 128 * FQ_STR;          // [64][68]
    float* Vs = Ks + 64 * FK_STR;             // [64][72]
    float* Ps = Vs + 64 * FV_STR;             // [128][68]

    const int qt   = (Ln / 128 - 1) - blockIdx.x;   // heavy tiles first
    const int h    = blockIdx.y;
    const int b_   = blockIdx.z;
    const int tid  = threadIdx.x;
    const int wid  = tid >> 5;
    const int lane = tid & 31;
    const int g    = lane >> 2;
    const int t4   = lane & 3;
    const int m0   = wid * 32;   // warp's query-row base within the 128-row tile

    const size_t base = ((size_t)b_ * Hn + h) * Ln * DHn;
    const float* Qb = Q + base;
    const float* Kb = K + base;
    const float* Vb = V + base;

    // Load Q tile (128 rows), pre-scaled by 1/sqrt(DH)=0.125 (exact pow2).
    for (int e = tid; e < 2048; e += 128) {
        const int r  = e >> 4;
        const int c4 = (e & 15) << 2;
        float4 qv = *reinterpret_cast<const float4*>(
            &Qb[(size_t)(qt * 128 + r) * DHn + c4]);
        qv.x *= 0.125f; qv.y *= 0.125f; qv.z *= 0.125f; qv.w *= 0.125f;
        *reinterpret_cast<float4*>(&Qs[r * FQ_STR + c4]) = qv;
    }

    // Row accumulators: j=0 -> row m0+g; j=1 -> +8; j=2 -> +16; j=3 -> +24
    float m_[4], l_[4];
    #pragma unroll
    for (int j = 0; j < 4; j++) { m_[j] = -1e30f; l_[j] = 0.f; }
    float o[2][8][4];
    #pragma unroll
    for (int mt = 0; mt < 2; mt++)
        #pragma unroll
        for (int nt = 0; nt < 8; nt++)
            #pragma unroll
            for (int r = 0; r < 4; r++) o[mt][nt][r] = 0.f;

    const int ktmax = 2 * qt + 1;
    for (int kt = 0; kt <= ktmax; kt++) {
        __syncthreads();   // previous iteration's K/V readers done
        for (int e = tid; e < 1024; e += 128) {
            const int r  = e >> 4;
            const int c4 = (e & 15) << 2;
            *reinterpret_cast<float4*>(&Ks[r * FK_STR + c4]) =
                *reinterpret_cast<const float4*>(
                    &Kb[(size_t)(kt * 64 + r) * DHn + c4]);
            *reinterpret_cast<float4*>(&Vs[r * FV_STR + c4]) =
                *reinterpret_cast<const float4*>(
                    &Vb[(size_t)(kt * 64 + r) * DHn + c4]);
        }
        __syncthreads();

        // ---- S = Q K^T ----
        float s[2][8][4];
        #pragma unroll
        for (int mt = 0; mt < 2; mt++)
            #pragma unroll
            for (int nt = 0; nt < 8; nt++)
                #pragma unroll
                for (int r = 0; r < 4; r++) s[mt][nt][r] = 0.f;

        #pragma unroll
        for (int ks = 0; ks < 8; ks++) {
            const int kk = ks * 8;
            uint32_t a0[4], a1[4];
            a0[0] = __float_as_uint(Qs[(m0 + g)      * FQ_STR + kk + t4]);
            a0[1] = __float_as_uint(Qs[(m0 + g + 8)  * FQ_STR + kk + t4]);
            a0[2] = __float_as_uint(Qs[(m0 + g)      * FQ_STR + kk + t4 + 4]);
            a0[3] = __float_as_uint(Qs[(m0 + g + 8)  * FQ_STR + kk + t4 + 4]);
            a1[0] = __float_as_uint(Qs[(m0 + g + 16) * FQ_STR + kk + t4]);
            a1[1] = __float_as_uint(Qs[(m0 + g + 24) * FQ_STR + kk + t4]);
            a1[2] = __float_as_uint(Qs[(m0 + g + 16) * FQ_STR + kk + t4 + 4]);
            a1[3] = __float_as_uint(Qs[(m0 + g + 24) * FQ_STR + kk + t4 + 4]);
            #pragma unroll
            for (int nt = 0; nt < 8; nt++) {
                uint32_t bfr[2];
                bfr[0] = __float_as_uint(Ks[(nt * 8 + g) * FK_STR + kk + t4]);
                bfr[1] = __float_as_uint(Ks[(nt * 8 + g) * FK_STR + kk + t4 + 4]);
                mma16n8k8(s[0][nt], a0, bfr);
                mma16n8k8(s[1][nt], a1, bfr);
            }
        }

        // ---- causal mask (diagonal spans kt = 2qt and 2qt+1) ----
        if (kt >= 2 * qt) {
            const int cbase = kt * 64 - qt * 128;   // col offset relative to row 0
            const int qr0 = m0 + g;
            #pragma unroll
            for (int nt = 0; nt < 8; nt++) {
                const int c0 = cbase + nt * 8 + 2 * t4;
                #pragma unroll
                for (int mt = 0; mt < 2; mt++) {
                    const int rA = qr0 + mt * 16;
                    const int rB = rA + 8;
                    if (c0     > rA) s[mt][nt][0] = -1e30f;
                    if (c0 + 1 > rA) s[mt][nt][1] = -1e30f;
                    if (c0     > rB) s[mt][nt][2] = -1e30f;
                    if (c0 + 1 > rB) s[mt][nt][3] = -1e30f;
                }
            }
        }

        // ---- online softmax: 4 rows per thread ----
        #pragma unroll
        for (int j = 0; j < 4; j++) {
            const int mt = j >> 1;
            const int lo = (j & 1) * 2;
            float mx = -1e30f;
            #pragma unroll
            for (int nt = 0; nt < 8; nt++)
                mx = fmaxf(mx, fmaxf(s[mt][nt][lo], s[mt][nt][lo + 1]));
            mx = fmaxf(mx, __shfl_xor_sync(0xffffffffu, mx, 1));
            mx = fmaxf(mx, __shfl_xor_sync(0xffffffffu, mx, 2));
            const float mnew  = fmaxf(m_[j], mx);
            const float alpha = __expf(m_[j] - mnew);
            float rs = 0.f;
            #pragma unroll
            for (int nt = 0; nt < 8; nt++) {
                const float p0 = __expf(s[mt][nt][lo]     - mnew);
                const float p1 = __expf(s[mt][nt][lo + 1] - mnew);
                s[mt][nt][lo]     = p0;
                s[mt][nt][lo + 1] = p1;
                rs += p0 + p1;
            }
            rs += __shfl_xor_sync(0xffffffffu, rs, 1);
            rs += __shfl_xor_sync(0xffffffffu, rs, 2);
            l_[j] = l_[j] * alpha + rs;
            m_[j] = mnew;
            #pragma unroll
            for (int nt = 0; nt < 8; nt++) {
                o[mt][nt][lo]     *= alpha;
                o[mt][nt][lo + 1] *= alpha;
            }
        }

        // ---- stage P (own 32 rows; only this warp reads them back) ----
        #pragma unroll
        for (int nt = 0; nt < 8; nt++) {
            const int cc = nt * 8 + 2 * t4;
            *reinterpret_cast<float2*>(&Ps[(m0 + g)      * FP_STR + cc]) =
                make_float2(rtf32(s[0][nt][0]), rtf32(s[0][nt][1]));
            *reinterpret_cast<float2*>(&Ps[(m0 + g + 8)  * FP_STR + cc]) =
                make_float2(rtf32(s[0][nt][2]), rtf32(s[0][nt][3]));
            *reinterpret_cast<float2*>(&Ps[(m0 + g + 16) * FP_STR + cc]) =
                make_float2(rtf32(s[1][nt][0]), rtf32(s[1][nt][1]));
            *reinterpret_cast<float2*>(&Ps[(m0 + g + 24) * FP_STR + cc]) =
                make_float2(rtf32(s[1][nt][2]), rtf32(s[1][nt][3]));
        }
        __syncwarp();

        // ---- O += P V ----
        #pragma unroll
        for (int ks = 0; ks < 8; ks++) {
            const int kk = ks * 8;
            uint32_t a0[4], a1[4];
            a0[0] = __float_as_uint(Ps[(m0 + g)      * FP_STR + kk + t4]);
            a0[1] = __float_as_uint(Ps[(m0 + g + 8)  * FP_STR + kk + t4]);
            a0[2] = __float_as_uint(Ps[(m0 + g)      * FP_STR + kk + t4 + 4]);
            a0[3] = __float_as_uint(Ps[(m0 + g + 8)  * FP_STR + kk + t4 + 4]);
            a1[0] = __float_as_uint(Ps[(m0 + g + 16) * FP_STR + kk + t4]);
            a1[1] = __float_as_uint(Ps[(m0 + g + 24) * FP_STR + kk + t4]);
            a1[2] = __float_as_uint(Ps[(m0 + g + 16) * FP_STR + kk + t4 + 4]);
            a1[3] = __float_as_uint(Ps[(m0 + g + 24) * FP_STR + kk + t4 + 4]);
            #pragma unroll
            for (int nt = 0; nt < 8; nt++) {
                uint32_t bfr[2];
                bfr[0] = __float_as_uint(Vs[(kk + t4)     * FV_STR + nt * 8 + g]);
                bfr[1] = __float_as_uint(Vs[(kk + t4 + 4) * FV_STR + nt * 8 + g]);
                mma16n8k8(o[0][nt], a0, bfr);
                mma16n8k8(o[1][nt], a1, bfr);
            }
        }
    }

    // ---- epilogue: normalize, tf32-round (feeds out-proj), write [B,L,D] ----
    #pragma unroll
    for (int j = 0; j < 4; j++) {
        const int mt = j >> 1;
        const int lo = (j & 1) * 2;
        const float inv = 1.0f / l_[j];
        const int row = qt * 128 + m0 + g + (j & 1) * 8 + (j >> 1) * 16;
        #pragma unroll
        for (int nt = 0; nt < 8; nt++) {
            const int col = h * DHn + nt * 8 + 2 * t4;
            *reinterpret_cast<float2*>(&O[((size_t)b_ * Ln + row) * Dn + col]) =
                make_float2(rtf32(o[mt][nt][lo] * inv),
                            rtf32(o[mt][nt][lo + 1] * inv));
        }
    }
}

// ---------------------------------------------------------------------------
// kernel_launch
// ---------------------------------------------------------------------------
extern "C" void kernel_launch(void* const* d_in, const int* in_sizes, int n_in,
                              void* d_out, int out_size)
{
    const float* x    = (const float*)d_in[0];
    // d_in[1] = mask (causal, known statically) — ignored
    const float* ln_g = (const float*)d_in[2];
    const float* ln_b = (const float*)d_in[3];
    const float* Wq   = (const float*)d_in[4];
    const float* bq   = (const float*)d_in[5];
    const float* Wk   = (const float*)d_in[6];
    const float* bk   = (const float*)d_in[7];
    const float* Wv   = (const float*)d_in[8];
    const float* bv   = (const float*)d_in[9];
    const float* Wo   = (const float*)d_in[10];
    const float* bo   = (const float*)d_in[11];
    float* out = (float*)d_out;

    float *ph, *pq, *pk, *pv, *po, *pw;
    cudaGetSymbolAddress((void**)&ph, g_h);
    cudaGetSymbolAddress((void**)&pq, g_q);
    cudaGetSymbolAddress((void**)&pk, g_k);
    cudaGetSymbolAddress((void**)&pv, g_v);
    cudaGetSymbolAddress((void**)&po, g_o);
    cudaGetSymbolAddress((void**)&pw, g_w);

    cudaFuncSetAttribute(qkv_gemm_kernel,
                         cudaFuncAttributeMaxDynamicSharedMemorySize, GEMM_SMEM);
    cudaFuncSetAttribute(out_gemm_kernel,
                         cudaFuncAttributeMaxDynamicSharedMemorySize, GEMM_SMEM);
    cudaFuncSetAttribute(flash_tf32_kernel,
                         cudaFuncAttributeMaxDynamicSharedMemorySize, FLASH_SMEM);

    // 0. Pre-round weights to tf32 (cvt-free cp.async GEMM mainloop)
    cvtw_kernel<<<dim3(Dn * Dn / 4 / 256, 1, 4), 256>>>(Wq, Wk, Wv, Wo, pw);

    // 1. LayerNorm (tf32-rounded output)
    ln_kernel<<<Mn, 256>>>(x, ln_g, ln_b, ph);

    // 2. QKV projections — single merged launch, grid.z selects matrix
    QKVArgs args;
    args.W[0] = pw;                   args.b[0] = bq;  args.out[0] = pq;
    args.W[1] = pw + (size_t)Dn*Dn;   args.b[1] = bk;  args.out[1] = pk;
    args.W[2] = pw + 2*(size_t)Dn*Dn; args.b[2] = bv;  args.out[2] = pv;
    qkv_gemm_kernel<<<dim3(Dn / 128, Mn / 128, 3), 128, GEMM_SMEM>>>(ph, args);

    // 3. Causal flash attention v2 (Br=128, warp-M=32; writes [B,L,D])
    dim3 fgrid(Ln / 128, Hn, Bn);
    flash_tf32_kernel<<<fgrid, 128, FLASH_SMEM>>>(pq, pk, pv, po);

    // 4. Output projection (fp32 row-major output)
    out_gemm_kernel<<<dim3(Dn / 128, Mn / 128), 128, GEMM_SMEM>>>(
        po, pw + 3*(size_t)Dn*Dn, bo, out);
}

// round 13
// speedup vs baseline: 4.2141x; 1.0424x over previous
#include <cuda_runtime.h>
#include <math.h>
#include <stdint.h>

// Problem constants
constexpr int Bn  = 2;
constexpr int Ln  = 2048;
constexpr int Dn  = 1024;
constexpr int Hn  = 16;
constexpr int DHn = 64;
constexpr int Mn  = Bn * Ln;   // 4096 rows

// Scratch (no cudaMalloc allowed)
__device__ float g_h[(size_t)Mn * Dn];
__device__ float g_q[(size_t)Mn * Dn];
__device__ float g_k[(size_t)Mn * Dn];
__device__ float g_v[(size_t)Mn * Dn];
__device__ float g_o[(size_t)Mn * Dn];
__device__ float g_w[4 * (size_t)Dn * Dn];   // tf32-rounded Wq,Wk,Wv,Wo

__device__ __forceinline__ uint32_t f2tf32(float f) {
    uint32_t u;
    asm("cvt.rna.tf32.f32 %0, %1;" : "=r"(u) : "f"(f));
    return u;
}
__device__ __forceinline__ float rtf32(float f) {
    return __uint_as_float(f2tf32(f));
}

__device__ __forceinline__ void mma16n8k8(float* d, const uint32_t* a, const uint32_t* b) {
    asm volatile(
        "mma.sync.aligned.m16n8k8.row.col.f32.tf32.tf32.f32 "
        "{%0,%1,%2,%3}, {%4,%5,%6,%7}, {%8,%9}, {%0,%1,%2,%3};"
        : "+f"(d[0]), "+f"(d[1]), "+f"(d[2]), "+f"(d[3])
        : "r"(a[0]), "r"(a[1]), "r"(a[2]), "r"(a[3]), "r"(b[0]), "r"(b[1]));
}

__device__ __forceinline__ void cp_async16(uint32_t dst, const float* src) {
    asm volatile("cp.async.cg.shared.global [%0], [%1], 16;"
                 :: "r"(dst), "l"(src) : "memory");
}

// ---------------------------------------------------------------------------
// Weight pre-round: tf32(rna) all four projection matrices into g_w.
// ---------------------------------------------------------------------------
__global__ __launch_bounds__(256) void cvtw_kernel(
    const float* __restrict__ Wq, const float* __restrict__ Wk,
    const float* __restrict__ Wv, const float* __restrict__ Wo,
    float* __restrict__ dst)
{
    const float* srcs[4] = {Wq, Wk, Wv, Wo};
    const float* s = srcs[blockIdx.z];
    float* d = dst + (size_t)blockIdx.z * Dn * Dn;
    const int i = blockIdx.x * 256 + threadIdx.x;   // float4 index
    float4 v = reinterpret_cast<const float4*>(s)[i];
    v.x = rtf32(v.x); v.y = rtf32(v.y); v.z = rtf32(v.z); v.w = rtf32(v.w);
    reinterpret_cast<float4*>(d)[i] = v;
}

// ---------------------------------------------------------------------------
// LayerNorm: one block per row, 256 threads, float4. Output tf32-rounded.
// ---------------------------------------------------------------------------
__global__ __launch_bounds__(256) void ln_kernel(
    const float* __restrict__ x, const float* __restrict__ gamma,
    const float* __restrict__ beta, float* __restrict__ out)
{
    const int row = blockIdx.x;
    const int t   = threadIdx.x;
    const float4 xv = reinterpret_cast<const float4*>(x + (size_t)row * Dn)[t];
    float s  = xv.x + xv.y + xv.z + xv.w;
    float sq = xv.x * xv.x + xv.y * xv.y + xv.z * xv.z + xv.w * xv.w;
    #pragma unroll
    for (int off = 16; off; off >>= 1) {
        s  += __shfl_xor_sync(0xffffffffu, s,  off);
        sq += __shfl_xor_sync(0xffffffffu, sq, off);
    }
    __shared__ float sh[16];
    if ((t & 31) == 0) { sh[t >> 5] = s; sh[8 + (t >> 5)] = sq; }
    __syncthreads();
    float S = 0.f, SQ = 0.f;
    #pragma unroll
    for (int i = 0; i < 8; i++) { S += sh[i]; SQ += sh[8 + i]; }
    const float mu   = S * (1.0f / Dn);
    const float var  = SQ * (1.0f / Dn) - mu * mu;
    const float rstd = rsqrtf(var + 1e-5f);
    const float4 gv = reinterpret_cast<const float4*>(gamma)[t];
    const float4 bv = reinterpret_cast<const float4*>(beta)[t];
    float4 ov;
    ov.x = rtf32((xv.x - mu) * rstd * gv.x + bv.x);
    ov.y = rtf32((xv.y - mu) * rstd * gv.y + bv.y);
    ov.z = rtf32((xv.z - mu) * rstd * gv.z + bv.z);
    ov.w = rtf32((xv.w - mu) * rstd * gv.w + bv.w);
    reinterpret_cast<float4*>(out + (size_t)row * Dn)[t] = ov;
}

// ---------------------------------------------------------------------------
// TF32 GEMM v3 (unchanged): BM=BN=128, BK=32, 128 threads = 4 warps (2x2),
// warp tile 64x64. 3-stage cp.async. A,B already tf32-rounded in gmem.
// ---------------------------------------------------------------------------
constexpr int STG_U   = 8960;                 // uints per stage (A 128x36 | B 32x136)
constexpr int GEMM_SMEM = 3 * STG_U * 4;      // 107,520 B

__device__ __forceinline__ size_t hs_addr(int m, int n) {
    const int b_ = m >> 11;
    const int l  = m & (Ln - 1);
    const int h  = n >> 6;
    const int dh = n & 63;
    return ((((size_t)b_ * Hn + h) * Ln) + l) * DHn + dh;
}

template <int OUT_MODE>
__device__ __forceinline__ void gemm_core(
    const float* __restrict__ A, const float* __restrict__ B,
    const float* __restrict__ bias, float* __restrict__ C)
{
    extern __shared__ uint32_t gsm[];

    const int tid  = threadIdx.x;
    const int bm   = blockIdx.y * 128;
    const int bn   = blockIdx.x * 128;
    const int wid  = tid >> 5;
    const int lane = tid & 31;
    const int wm   = (wid >> 1) * 64;   // 0 or 64
    const int wn   = (wid & 1) * 64;    // 0 or 64
    const int g    = lane >> 2;
    const int t4   = lane & 3;

    const uint32_t smem_base = (uint32_t)__cvta_generic_to_shared(gsm);

    float acc[4][8][4];
    #pragma unroll
    for (int i = 0; i < 4; i++)
        #pragma unroll
        for (int j = 0; j < 8; j++)
            #pragma unroll
            for (int r = 0; r < 4; r++) acc[i][j][r] = 0.f;

    auto issue = [&](int t, int stage) {
        const uint32_t sb = smem_base + stage * (STG_U * 4);
        #pragma unroll
        for (int i = 0; i < 8; i++) {
            const int e  = tid + i * 128;
            const int ar = e >> 3, ac4 = (e & 7) << 2;
            cp_async16(sb + (ar * 36 + ac4) * 4,
                       A + (size_t)(bm + ar) * Dn + t * 32 + ac4);
            const int kb = e >> 5, n4 = (e & 31) << 2;
            cp_async16(sb + (4608 + kb * 136 + n4) * 4,
                       B + (size_t)(t * 32 + kb) * Dn + bn + n4);
        }
        asm volatile("cp.async.commit_group;" ::: "memory");
    };

    issue(0, 0);
    issue(1, 1);

    constexpr int NITER = Dn / 32;   // 32
    for (int t = 0; t < NITER; t++) {
        if (t < NITER - 1)
            asm volatile("cp.async.wait_group 1;" ::: "memory");
        else
            asm volatile("cp.async.wait_group 0;" ::: "memory");
        __syncthreads();
        if (t + 2 < NITER) issue(t + 2, (t + 2) % 3);

        const uint32_t* As = gsm + (t % 3) * STG_U;
        const uint32_t* Bs = As + 4608;

        #pragma unroll
        for (int ks = 0; ks < 4; ks++) {
            const int kk = ks * 8;
            uint32_t af[4][4];
            #pragma unroll
            for (int i = 0; i < 4; i++) {
                const int r = wm + i * 16 + g;
                af[i][0] = As[r * 36 + kk + t4];
                af[i][1] = As[(r + 8) * 36 + kk + t4];
                af[i][2] = As[r * 36 + kk + t4 + 4];
                af[i][3] = As[(r + 8) * 36 + kk + t4 + 4];
            }
            uint32_t bf[8][2];
            #pragma unroll
            for (int j = 0; j < 8; j++) {
                const int n = wn + j * 8 + g;
                bf[j][0] = Bs[(kk + t4) * 136 + n];
                bf[j][1] = Bs[(kk + t4 + 4) * 136 + n];
            }
            #pragma unroll
            for (int i = 0; i < 4; i++)
                #pragma unroll
                for (int j = 0; j < 8; j++)
                    mma16n8k8(acc[i][j], af[i], bf[j]);
        }
    }

    #pragma unroll
    for (int i = 0; i < 4; i++) {
        #pragma unroll
        for (int j = 0; j < 8; j++) {
            const int m0 = bm + wm + i * 16 + g;
            const int n0 = bn + wn + j * 8 + t4 * 2;
            const float b0 = bias[n0], b1 = bias[n0 + 1];
            if (OUT_MODE == 0) {
                const float2 v0 = make_float2(acc[i][j][0] + b0, acc[i][j][1] + b1);
                const float2 v1 = make_float2(acc[i][j][2] + b0, acc[i][j][3] + b1);
                *reinterpret_cast<float2*>(&C[(size_t)m0 * Dn + n0])       = v0;
                *reinterpret_cast<float2*>(&C[(size_t)(m0 + 8) * Dn + n0]) = v1;
            } else {
                const float2 v0 = make_float2(rtf32(acc[i][j][0] + b0),
                                              rtf32(acc[i][j][1] + b1));
                const float2 v1 = make_float2(rtf32(acc[i][j][2] + b0),
                                              rtf32(acc[i][j][3] + b1));
                *reinterpret_cast<float2*>(&C[hs_addr(m0, n0)])     = v0;
                *reinterpret_cast<float2*>(&C[hs_addr(m0 + 8, n0)]) = v1;
            }
        }
    }
}

struct QKVArgs {
    const float* W[3];
    const float* b[3];
    float*       out[3];
};

__global__ __launch_bounds__(128, 2) void qkv_gemm_kernel(
    const float* __restrict__ A, QKVArgs args)
{
    const int z = blockIdx.z;
    gemm_core<1>(A, args.W[z], args.b[z], args.out[z]);
}

__global__ __launch_bounds__(128, 2) void out_gemm_kernel(
    const float* __restrict__ A, const float* __restrict__ W,
    const float* __restrict__ bias, float* __restrict__ C)
{
    gemm_core<0>(A, W, bias, C);
}

// ---------------------------------------------------------------------------
// Flash attention v3 (causal), tf32 tensor cores.
// Br=128, Bc=64, 4 warps x 32 query rows.
//  - Q fragments hoisted to registers (loop-invariant across kt)
//  - P accumulator->A-fragment via quad shuffles (no smem round-trip)
//  - 3-stage cp.async K/V ring, ONE __syncthreads per kt iteration
// smem: 3 x (K[64][68] + V[64][72]) = 107,520 B -> 2 CTAs/SM.
// ---------------------------------------------------------------------------
constexpr int FK_STR = 68;
constexpr int FV_STR = 72;
constexpr int FSTG   = 64 * FK_STR + 64 * FV_STR;   // 8960 floats/stage
constexpr int FLASH_SMEM = 3 * FSTG * 4;            // 107,520 B

__global__ __launch_bounds__(128, 2) void flash_tf32_kernel(
    const float* __restrict__ Q, const float* __restrict__ K,
    const float* __restrict__ V, float* __restrict__ O)
{
    extern __shared__ float smem[];

    const int qt   = (Ln / 128 - 1) - blockIdx.x;   // heavy tiles first
    const int h    = blockIdx.y;
    const int b_   = blockIdx.z;
    const int tid  = threadIdx.x;
    const int wid  = tid >> 5;
    const int lane = tid & 31;
    const int g    = lane >> 2;
    const int t4   = lane & 3;
    const int m0   = wid * 32;

    const size_t base = ((size_t)b_ * Hn + h) * Ln * DHn;
    const float* Qb = Q + base;
    const float* Kb = K + base;
    const float* Vb = V + base;

    const uint32_t smem_b = (uint32_t)__cvta_generic_to_shared(smem);

    // ---- Stage Q into smem (stride FK_STR), pre-scaled by 1/8; then hoist
    //      this warp's A-fragments into registers. Q smem is then dead. ----
    for (int e = tid; e < 2048; e += 128) {
        const int r  = e >> 4;
        const int c4 = (e & 15) << 2;
        float4 qv = *reinterpret_cast<const float4*>(
            &Qb[(size_t)(qt * 128 + r) * DHn + c4]);
        qv.x *= 0.125f; qv.y *= 0.125f; qv.z *= 0.125f; qv.w *= 0.125f;
        *reinterpret_cast<float4*>(&smem[r * FK_STR + c4]) = qv;
    }
    __syncthreads();

    uint32_t qf[2][8][4];
    #pragma unroll
    for (int mt = 0; mt < 2; mt++) {
        const int rA = m0 + mt * 16 + g;
        const int rB = rA + 8;
        #pragma unroll
        for (int ks = 0; ks < 8; ks++) {
            const int kk = ks * 8;
            qf[mt][ks][0] = __float_as_uint(smem[rA * FK_STR + kk + t4]);
            qf[mt][ks][1] = __float_as_uint(smem[rB * FK_STR + kk + t4]);
            qf[mt][ks][2] = __float_as_uint(smem[rA * FK_STR + kk + t4 + 4]);
            qf[mt][ks][3] = __float_as_uint(smem[rB * FK_STR + kk + t4 + 4]);
        }
    }
    __syncthreads();

    // ---- accumulators ----
    float m_[4], l_[4];
    #pragma unroll
    for (int j = 0; j < 4; j++) { m_[j] = -1e30f; l_[j] = 0.f; }
    float o[2][8][4];
    #pragma unroll
    for (int mt = 0; mt < 2; mt++)
        #pragma unroll
        for (int nt = 0; nt < 8; nt++)
            #pragma unroll
            for (int r = 0; r < 4; r++) o[mt][nt][r] = 0.f;

    // ---- cp.async K/V ring ----
    auto issueKV = [&](int kt, int stg) {
        const uint32_t kd = smem_b + stg * (FSTG * 4);
        const uint32_t vd = kd + 64 * FK_STR * 4;
        #pragma unroll
        for (int i = 0; i < 8; i++) {
            const int e  = tid + i * 128;
            const int r  = e >> 4;
            const int c4 = (e & 15) << 2;
            cp_async16(kd + (r * FK_STR + c4) * 4,
                       Kb + (size_t)(kt * 64 + r) * DHn + c4);
            cp_async16(vd + (r * FV_STR + c4) * 4,
                       Vb + (size_t)(kt * 64 + r) * DHn + c4);
        }
        asm volatile("cp.async.commit_group;" ::: "memory");
    };

    const int ktmax = 2 * qt + 1;
    issueKV(0, 0);
    issueKV(1, 1);

    for (int kt = 0; kt <= ktmax; kt++) {
        if (kt < ktmax)
            asm volatile("cp.async.wait_group 1;" ::: "memory");
        else
            asm volatile("cp.async.wait_group 0;" ::: "memory");
        __syncthreads();
        if (kt + 2 <= ktmax) issueKV(kt + 2, (kt + 2) % 3);

        const float* Ks = smem + (kt % 3) * FSTG;
        const float* Vs = Ks + 64 * FK_STR;

        // ---- S = Q K^T ----
        float s[2][8][4];
        #pragma unroll
        for (int mt = 0; mt < 2; mt++)
            #pragma unroll
            for (int nt = 0; nt < 8; nt++)
                #pragma unroll
                for (int r = 0; r < 4; r++) s[mt][nt][r] = 0.f;

        #pragma unroll
        for (int ks = 0; ks < 8; ks++) {
            const int kk = ks * 8;
            #pragma unroll
            for (int nt = 0; nt < 8; nt++) {
                uint32_t bfr[2];
                bfr[0] = __float_as_uint(Ks[(nt * 8 + g) * FK_STR + kk + t4]);
                bfr[1] = __float_as_uint(Ks[(nt * 8 + g) * FK_STR + kk + t4 + 4]);
                mma16n8k8(s[0][nt], qf[0][ks], bfr);
                mma16n8k8(s[1][nt], qf[1][ks], bfr);
            }
        }

        // ---- causal mask (diagonal spans kt = 2qt and 2qt+1) ----
        if (kt >= 2 * qt) {
            const int cbase = kt * 64 - qt * 128;
            const int qr0 = m0 + g;
            #pragma unroll
            for (int nt = 0; nt < 8; nt++) {
                const int c0 = cbase + nt * 8 + 2 * t4;
                #pragma unroll
                for (int mt = 0; mt < 2; mt++) {
                    const int rA = qr0 + mt * 16;
                    const int rB = rA + 8;
                    if (c0     > rA) s[mt][nt][0] = -1e30f;
                    if (c0 + 1 > rA) s[mt][nt][1] = -1e30f;
                    if (c0     > rB) s[mt][nt][2] = -1e30f;
                    if (c0 + 1 > rB) s[mt][nt][3] = -1e30f;
                }
            }
        }

        // ---- online softmax: 4 rows per thread ----
        #pragma unroll
        for (int j = 0; j < 4; j++) {
            const int mt = j >> 1;
            const int lo = (j & 1) * 2;
            float mx = -1e30f;
            #pragma unroll
            for (int nt = 0; nt < 8; nt++)
                mx = fmaxf(mx, fmaxf(s[mt][nt][lo], s[mt][nt][lo + 1]));
            mx = fmaxf(mx, __shfl_xor_sync(0xffffffffu, mx, 1));
            mx = fmaxf(mx, __shfl_xor_sync(0xffffffffu, mx, 2));
            const float mnew  = fmaxf(m_[j], mx);
            const float alpha = __expf(m_[j] - mnew);
            float rs = 0.f;
            #pragma unroll
            for (int nt = 0; nt < 8; nt++) {
                const float p0 = __expf(s[mt][nt][lo]     - mnew);
                const float p1 = __expf(s[mt][nt][lo + 1] - mnew);
                s[mt][nt][lo]     = p0;
                s[mt][nt][lo + 1] = p1;
                rs += p0 + p1;
            }
            rs += __shfl_xor_sync(0xffffffffu, rs, 1);
            rs += __shfl_xor_sync(0xffffffffu, rs, 2);
            l_[j] = l_[j] * alpha + rs;
            m_[j] = mnew;
            #pragma unroll
            for (int nt = 0; nt < 8; nt++) {
                o[mt][nt][lo]     *= alpha;
                o[mt][nt][lo + 1] *= alpha;
            }
        }

        // ---- round P to tf32 in-register (same rounding point as before) ----
        #pragma unroll
        for (int mt = 0; mt < 2; mt++)
            #pragma unroll
            for (int nt = 0; nt < 8; nt++)
                #pragma unroll
                for (int r = 0; r < 4; r++)
                    s[mt][nt][r] = rtf32(s[mt][nt][r]);

        // ---- O += P V : P A-fragments built by quad shuffles ----
        // accum (g',t4') holds cols {2t4',2t4'+1}; A-frag needs cols t4, t4+4.
        const int srcA = 4 * g + (t4 >> 1);
        const int srcB = srcA + 2;
        const bool odd = (t4 & 1);
        #pragma unroll
        for (int ks = 0; ks < 8; ks++) {
            const int kk = ks * 8;
            uint32_t af[2][4];
            #pragma unroll
            for (int mt = 0; mt < 2; mt++) {
                const float x0 = __shfl_sync(0xffffffffu, s[mt][ks][0], srcA);
                const float x1 = __shfl_sync(0xffffffffu, s[mt][ks][1], srcA);
                const float x2 = __shfl_sync(0xffffffffu, s[mt][ks][2], srcA);
                const float x3 = __shfl_sync(0xffffffffu, s[mt][ks][3], srcA);
                const float y0 = __shfl_sync(0xffffffffu, s[mt][ks][0], srcB);
                const float y1 = __shfl_sync(0xffffffffu, s[mt][ks][1], srcB);
                const float y2 = __shfl_sync(0xffffffffu, s[mt][ks][2], srcB);
                const float y3 = __shfl_sync(0xffffffffu, s[mt][ks][3], srcB);
                af[mt][0] = __float_as_uint(odd ? x1 : x0);
                af[mt][1] = __float_as_uint(odd ? x3 : x2);
                af[mt][2] = __float_as_uint(odd ? y1 : y0);
                af[mt][3] = __float_as_uint(odd ? y3 : y2);
            }
            #pragma unroll
            for (int nt = 0; nt < 8; nt++) {
                uint32_t bfr[2];
                bfr[0] = __float_as_uint(Vs[(kk + t4)     * FV_STR + nt * 8 + g]);
                bfr[1] = __float_as_uint(Vs[(kk + t4 + 4) * FV_STR + nt * 8 + g]);
                mma16n8k8(o[0][nt], af[0], bfr);
                mma16n8k8(o[1][nt], af[1], bfr);
            }
        }
    }

    // ---- epilogue: normalize, tf32-round (feeds out-proj), write [B,L,D] ----
    #pragma unroll
    for (int j = 0; j < 4; j++) {
        const int mt = j >> 1;
        const int lo = (j & 1) * 2;
        const float inv = 1.0f / l_[j];
        const int row = qt * 128 + m0 + g + (j & 1) * 8 + (j >> 1) * 16;
        #pragma unroll
        for (int nt = 0; nt < 8; nt++) {
            const int col = h * DHn + nt * 8 + 2 * t4;
            *reinterpret_cast<float2*>(&O[((size_t)b_ * Ln + row) * Dn + col]) =
                make_float2(rtf32(o[mt][nt][lo] * inv),
                            rtf32(o[mt][nt][lo + 1] * inv));
        }
    }
}

// ---------------------------------------------------------------------------
// kernel_launch
// ---------------------------------------------------------------------------
extern "C" void kernel_launch(void* const* d_in, const int* in_sizes, int n_in,
                              void* d_out, int out_size)
{
    const float* x    = (const float*)d_in[0];
    // d_in[1] = mask (causal, known statically) — ignored
    const float* ln_g = (const float*)d_in[2];
    const float* ln_b = (const float*)d_in[3];
    const float* Wq   = (const float*)d_in[4];
    const float* bq   = (const float*)d_in[5];
    const float* Wk   = (const float*)d_in[6];
    const float* bk   = (const float*)d_in[7];
    const float* Wv   = (const float*)d_in[8];
    const float* bv   = (const float*)d_in[9];
    const float* Wo   = (const float*)d_in[10];
    const float* bo   = (const float*)d_in[11];
    float* out = (float*)d_out;

    float *ph, *pq, *pk, *pv, *po, *pw;
    cudaGetSymbolAddress((void**)&ph, g_h);
    cudaGetSymbolAddress((void**)&pq, g_q);
    cudaGetSymbolAddress((void**)&pk, g_k);
    cudaGetSymbolAddress((void**)&pv, g_v);
    cudaGetSymbolAddress((void**)&po, g_o);
    cudaGetSymbolAddress((void**)&pw, g_w);

    cudaFuncSetAttribute(qkv_gemm_kernel,
                         cudaFuncAttributeMaxDynamicSharedMemorySize, GEMM_SMEM);
    cudaFuncSetAttribute(out_gemm_kernel,
                         cudaFuncAttributeMaxDynamicSharedMemorySize, GEMM_SMEM);
    cudaFuncSetAttribute(flash_tf32_kernel,
                         cudaFuncAttributeMaxDynamicSharedMemorySize, FLASH_SMEM);

    // 0. Pre-round weights to tf32 (cvt-free cp.async GEMM mainloop)
    cvtw_kernel<<<dim3(Dn * Dn / 4 / 256, 1, 4), 256>>>(Wq, Wk, Wv, Wo, pw);

    // 1. LayerNorm (tf32-rounded output)
    ln_kernel<<<Mn, 256>>>(x, ln_g, ln_b, ph);

    // 2. QKV projections — single merged launch, grid.z selects matrix
    QKVArgs args;
    args.W[0] = pw;                   args.b[0] = bq;  args.out[0] = pq;
    args.W[1] = pw + (size_t)Dn*Dn;   args.b[1] = bk;  args.out[1] = pk;
    args.W[2] = pw + 2*(size_t)Dn*Dn; args.b[2] = bv;  args.out[2] = pv;
    qkv_gemm_kernel<<<dim3(Dn / 128, Mn / 128, 3), 128, GEMM_SMEM>>>(ph, args);

    // 3. Causal flash attention v3 (pipelined KV, reg-resident Q/P)
    dim3 fgrid(Ln / 128, Hn, Bn);
    flash_tf32_kernel<<<fgrid, 128, FLASH_SMEM>>>(pq, pk, pv, po);

    // 4. Output projection (fp32 row-major output)
    out_gemm_kernel<<<dim3(Dn / 128, Mn / 128), 128, GEMM_SMEM>>>(
        po, pw + 3*(size_t)Dn*Dn, bo, out);
}